// round 3
// baseline (speedup 1.0000x reference)
#include <cuda_runtime.h>
#include <math.h>

typedef unsigned long long ull;

#define Bn 2048
#define Sn 50
#define En 300
#define Tn 8
#define Cn 4
#define Un 300
#define Ln 1000
#define NPAIR 44850
#define KPAD  44864      // NPAIR padded to multiple of 32
#define NOP   320        // fc7 output cols padded (300 -> 320)
#define EPSf  1e-5f
#define PADVAL (-4294967295.0f)
#define KSPLIT 8
#define NCHUNK (KPAD/32) // 1402

// ------------------------- scratch (device globals) -------------------------
__device__ float d_W7gT[(size_t)KPAD * NOP];   // 57.4 MB: fc7_w^T * g, zero-padded
__device__ unsigned int d_pairs[KPAD];
__device__ float d_g[NPAIR];
__device__ float d_Aq [2][Bn*Sn];
__device__ float d_Asm[2][Bn*Sn];
__device__ float d_Asq[2][Bn*Sn];
__device__ float d_sgn[Bn*Sn];
__device__ float d_m [2][Sn];
__device__ float d_is[2][Sn];
__device__ float d_Q [2];
__device__ float d_h   [(size_t)Bn*600];
__device__ float d_h5  [(size_t)Bn*En];
__device__ float d_h6p [(size_t)Bn*En];
__device__ float d_h7p [(size_t)Bn*En];
__device__ float d_hcat[(size_t)Bn*600];
__device__ float d_out8[(size_t)Bn*Un];
__device__ float d_cm[1024], d_cis[1024];

// ------------------------- f32x2 packed helpers -----------------------------
__device__ __forceinline__ ull pack2(float x, float y) {
    ull r; asm("mov.b64 %0, {%1,%2};" : "=l"(r) : "f"(x), "f"(y)); return r;
}
__device__ __forceinline__ float2 unpk(ull v) {
    float2 r; asm("mov.b64 {%0,%1}, %2;" : "=f"(r.x), "=f"(r.y) : "l"(v)); return r;
}
__device__ __forceinline__ void ffma2(ull &d, ull a, ull b) {
    asm("fma.rn.f32x2 %0, %1, %2, %0;" : "+l"(d) : "l"(a), "l"(b));
}

// ------------------------- prep: pair indices + g ---------------------------
__device__ __forceinline__ long long pair_off(long long i) {
    return i * (2LL*En - i - 1) / 2;
}

__global__ void pair_kernel(const float* __restrict__ v) {
    int p = blockIdx.x * 256 + threadIdx.x;
    if (p >= KPAD) return;
    if (p >= NPAIR) { d_pairs[p] = 0; return; }
    double a = 2.0*En - 1.0;
    int i = (int)((a - sqrt(a*a - 8.0*(double)p)) * 0.5);
    if (i < 0) i = 0; if (i > En-2) i = En-2;
    while (i > 0 && pair_off(i) > p) i--;
    while (i < En-2 && pair_off(i+1) <= p) i++;
    int j = i + 1 + (int)((long long)p - pair_off(i));
    d_pairs[p] = ((unsigned)i << 16) | (unsigned)j;
    float g = 0.f;
    #pragma unroll
    for (int c = 0; c < Cn; c++) g += v[i*Cn+c] * v[j*Cn+c];
    d_g[p] = g;
}

// transpose fc7_w [300, NPAIR] -> W7gT [KPAD, 320], scaled by g[p], zero pad
__global__ void w7g_kernel(const float* __restrict__ fc7_w) {
    __shared__ float tile[32][33];
    int p0 = blockIdx.x * 32, o0 = blockIdx.y * 32;
    int tx = threadIdx.x, ty = threadIdx.y;
    int o = o0 + ty, p = p0 + tx;
    tile[ty][tx] = (o < En && p < NPAIR) ? fc7_w[(size_t)o*NPAIR + p] : 0.f;
    __syncthreads();
    int pw = p0 + ty, ow = o0 + tx;
    float gv = (pw < NPAIR) ? d_g[pw] : 0.f;
    d_W7gT[(size_t)pw*NOP + ow] = tile[tx][ty] * gv;
}

// ------------------------- attention pass 1 ---------------------------------
__global__ void attn_kernel(const float* __restrict__ x,
                            const float* __restrict__ w1, const float* __restrict__ b1,
                            const float* __restrict__ q1,
                            const float* __restrict__ w3, const float* __restrict__ b3,
                            const float* __restrict__ q3) {
    __shared__ float ws[16*En];
    __shared__ float bs[16], qs[16];
    int tid = threadIdx.x;
    for (int idx = tid; idx < 16*En; idx += blockDim.x) {
        int t = idx / En, e = idx % En;
        ws[idx] = (t < 8) ? w1[t*En + e] : w3[(t-8)*En + e];
    }
    if (tid < 8)       { bs[tid] = b1[tid];   qs[tid] = q1[tid]; }
    else if (tid < 16) { bs[tid] = b3[tid-8]; qs[tid] = q3[tid-8]; }
    __syncthreads();

    int lane = tid & 31;
    int gw = blockIdx.x * (blockDim.x >> 5) + (tid >> 5);
    int nw = gridDim.x * (blockDim.x >> 5);
    for (int item = gw; item < Bn*Sn; item += nw) {
        const float* xp = x + (size_t)item * En;
        float dot[16];
        #pragma unroll
        for (int t = 0; t < 16; t++) dot[t] = 0.f;
        float ab = 0.f;
        for (int e = lane; e < En; e += 32) {
            float xv = xp[e];
            ab += fabsf(xv);
            #pragma unroll
            for (int t = 0; t < 16; t++) dot[t] += xv * ws[t*En + e];
        }
        #pragma unroll
        for (int o = 16; o > 0; o >>= 1) {
            ab += __shfl_down_sync(0xffffffffu, ab, o);
            #pragma unroll
            for (int t = 0; t < 16; t++) dot[t] += __shfl_down_sync(0xffffffffu, dot[t], o);
        }
        if (lane == 0) {
            #pragma unroll
            for (int h = 0; h < 2; h++) {
                float asum = 0.f, asq = 0.f, aq = 0.f;
                #pragma unroll
                for (int t = 0; t < 8; t++) {
                    float av = dot[h*8+t] + bs[h*8+t];
                    av = av > 0.f ? av : 0.f;
                    asum += av; asq += av*av; aq += av * qs[h*8+t];
                }
                d_Aq[h][item] = aq; d_Asm[h][item] = asum; d_Asq[h][item] = asq;
            }
            d_sgn[item] = ab;
        }
    }
}

// per-s BN stats over (b, t)  — deterministic reduction
__global__ void attn_stats_kernel(const float* __restrict__ q1,
                                  const float* __restrict__ q3) {
    int s = blockIdx.x, h = blockIdx.y;
    __shared__ float r1[256], r2[256];
    float a = 0.f, b = 0.f;
    for (int bb = threadIdx.x; bb < Bn; bb += 256) {
        a += d_Asm[h][bb*Sn + s];
        b += d_Asq[h][bb*Sn + s];
    }
    r1[threadIdx.x] = a; r2[threadIdx.x] = b; __syncthreads();
    for (int o = 128; o > 0; o >>= 1) {
        if (threadIdx.x < o) { r1[threadIdx.x] += r1[threadIdx.x+o]; r2[threadIdx.x] += r2[threadIdx.x+o]; }
        __syncthreads();
    }
    if (threadIdx.x == 0) {
        float n = (float)(Bn * Tn);
        float m = r1[0] / n;
        float var = r2[0] / n - m*m;
        d_m[h][s] = m;
        d_is[h][s] = rsqrtf(var + EPSf);
        if (s == 0) {
            const float* q = h ? q3 : q1;
            float Q = 0.f;
            for (int t = 0; t < 8; t++) Q += q[t];
            d_Q[h] = Q;
        }
    }
}

// ------------------------- softmax + pooling (pass 2 over x) ----------------
__global__ void pool_kernel(const float* __restrict__ x) {
    int b = blockIdx.x;
    __shared__ float w0[Sn], w1s[Sn];
    int tid = threadIdx.x;
    if (tid < Sn) {
        int item = b*Sn + tid;
        float sg = d_sgn[item];
        float s0 = (sg == 0.f) ? PADVAL : (d_Aq[0][item] - d_m[0][tid]*d_Q[0]) * d_is[0][tid];
        float s1 = (sg == 0.f) ? PADVAL : (d_Aq[1][item] - d_m[1][tid]*d_Q[1]) * d_is[1][tid];
        w0[tid] = s0; w1s[tid] = s1;
    }
    __syncthreads();
    float mx0 = -INFINITY, mx1 = -INFINITY;
    for (int s = 0; s < Sn; s++) { mx0 = fmaxf(mx0, w0[s]); mx1 = fmaxf(mx1, w1s[s]); }
    __syncthreads();
    if (tid < Sn) { w0[tid] = expf(w0[tid]-mx0); w1s[tid] = expf(w1s[tid]-mx1); }
    __syncthreads();
    float sm0 = 0.f, sm1 = 0.f;
    for (int s = 0; s < Sn; s++) { sm0 += w0[s]; sm1 += w1s[s]; }
    float inv0 = 1.f/sm0, inv1 = 1.f/sm1;
    if (tid < En) {
        float a0 = 0.f, a1 = 0.f;
        const float* xp = x + (size_t)b*Sn*En + tid;
        for (int s = 0; s < Sn; s++) {
            float xv = xp[(size_t)s*En];
            a0 += w0[s]*xv; a1 += w1s[s]*xv;
        }
        d_h[(size_t)b*600 + tid]       = a0*inv0;
        d_h[(size_t)b*600 + 300 + tid] = a1*inv1;
    }
}

// ------------------------- generic SGEMM  C[M,N] = A[M,K] @ W[N,K]^T (+bias) -
// BM=64 BN=64 BK=12, 256 threads, 4x4 micro-tile via f32x2 packed FMA
__global__ void gemm_kernel(const float* __restrict__ A, const float* __restrict__ W,
                            float* __restrict__ Cout, const float* __restrict__ bias,
                            int N, int K) {
    __shared__ float As[12*68];
    __shared__ float Ws[12*68];
    int m0 = blockIdx.y * 64, n0 = blockIdx.x * 64;
    int tid = threadIdx.x;
    int ty = tid >> 4, tx = tid & 15;
    ull acc[4][2];
    #pragma unroll
    for (int i = 0; i < 4; i++) { acc[i][0] = 0ULL; acc[i][1] = 0ULL; }

    for (int kc = 0; kc < K; kc += 12) {
        for (int idx = tid; idx < 64*12; idx += 256) {
            int r = idx / 12, kk = idx % 12;
            As[kk*68 + r] = A[(size_t)(m0+r)*K + kc + kk];
        }
        for (int idx = tid; idx < 64*12; idx += 256) {
            int c = idx / 12, kk = idx % 12;
            int col = n0 + c;
            Ws[kk*68 + c] = (col < N) ? W[(size_t)col*K + kc + kk] : 0.f;
        }
        __syncthreads();
        #pragma unroll
        for (int kk = 0; kk < 12; kk++) {
            float4 av = *(const float4*)&As[kk*68 + ty*4];
            float4 bv = *(const float4*)&Ws[kk*68 + tx*4];
            ull b01 = pack2(bv.x, bv.y), b23 = pack2(bv.z, bv.w);
            ull a;
            a = pack2(av.x, av.x); ffma2(acc[0][0], a, b01); ffma2(acc[0][1], a, b23);
            a = pack2(av.y, av.y); ffma2(acc[1][0], a, b01); ffma2(acc[1][1], a, b23);
            a = pack2(av.z, av.z); ffma2(acc[2][0], a, b01); ffma2(acc[2][1], a, b23);
            a = pack2(av.w, av.w); ffma2(acc[3][0], a, b01); ffma2(acc[3][1], a, b23);
        }
        __syncthreads();
    }
    #pragma unroll
    for (int i = 0; i < 4; i++) {
        int row = m0 + ty*4 + i;
        #pragma unroll
        for (int jj = 0; jj < 2; jj++) {
            float2 vv = unpk(acc[i][jj]);
            int col = n0 + tx*4 + jj*2;
            if (col < N)     Cout[(size_t)row*N + col]     = vv.x + (bias ? bias[col]   : 0.f);
            if (col + 1 < N) Cout[(size_t)row*N + col + 1] = vv.y + (bias ? bias[col+1] : 0.f);
        }
    }
}

// ------------------------- fc7 fused cross-GEMM -----------------------------
// C[b,o] += sum_p h5[b,i_p]*h5[b,j_p] * W7gT[p,o]; split-K over blockIdx.z
__global__ void fc7_kernel() {
    extern __shared__ float sm[];
    float* h5s = sm;                                // 64*301
    float* As  = sm + 64*301;                       // 32*68
    float* Bs  = As + 32*68;                        // 32*68
    unsigned int* pair_s = (unsigned int*)(Bs + 32*68); // 32

    int m0 = blockIdx.y * 64;
    int n0 = blockIdx.x * 64;
    int tid = threadIdx.x;
    int ty = tid >> 4, tx = tid & 15;

    for (int idx = tid; idx < 64*En; idx += 256) {
        int r = idx / En, e = idx % En;
        h5s[r*301 + e] = d_h5[(size_t)(m0+r)*En + e];
    }
    __syncthreads();

    ull acc[4][2];
    #pragma unroll
    for (int i = 0; i < 4; i++) { acc[i][0] = 0ULL; acc[i][1] = 0ULL; }

    const int per = (NCHUNK + KSPLIT - 1) / KSPLIT;     // 176
    int c0 = blockIdx.z * per;
    int c1 = c0 + per; if (c1 > NCHUNK) c1 = NCHUNK;

    for (int kc = c0; kc < c1; kc++) {
        int k0 = kc * 32;
        if (tid < 32) pair_s[tid] = d_pairs[k0 + tid];
        #pragma unroll
        for (int t = 0; t < 8; t++) {
            int idx = tid + t*256;
            int kk = idx >> 6, col = idx & 63;
            Bs[kk*68 + col] = d_W7gT[(size_t)(k0+kk)*NOP + n0 + col];
        }
        __syncthreads();
        #pragma unroll
        for (int t = 0; t < 8; t++) {
            int idx = tid + t*256;
            int row = idx & 63, kk = idx >> 6;
            unsigned int pp = pair_s[kk];
            int i = pp >> 16, j = pp & 0xFFFF;
            As[kk*68 + row] = h5s[row*301 + i] * h5s[row*301 + j];
        }
        __syncthreads();
        #pragma unroll
        for (int kk = 0; kk < 32; kk++) {
            float4 av = *(const float4*)&As[kk*68 + ty*4];
            float4 bv = *(const float4*)&Bs[kk*68 + tx*4];
            ull b01 = pack2(bv.x, bv.y), b23 = pack2(bv.z, bv.w);
            ull a;
            a = pack2(av.x, av.x); ffma2(acc[0][0], a, b01); ffma2(acc[0][1], a, b23);
            a = pack2(av.y, av.y); ffma2(acc[1][0], a, b01); ffma2(acc[1][1], a, b23);
            a = pack2(av.z, av.z); ffma2(acc[2][0], a, b01); ffma2(acc[2][1], a, b23);
            a = pack2(av.w, av.w); ffma2(acc[3][0], a, b01); ffma2(acc[3][1], a, b23);
        }
        __syncthreads();
    }
    #pragma unroll
    for (int i = 0; i < 4; i++) {
        int row = m0 + ty*4 + i;
        #pragma unroll
        for (int jj = 0; jj < 2; jj++) {
            float2 vv = unpk(acc[i][jj]);
            int col = n0 + tx*4 + jj*2;
            if (col < En)     atomicAdd(&d_h7p[(size_t)row*En + col],     vv.x);
            if (col + 1 < En) atomicAdd(&d_h7p[(size_t)row*En + col + 1], vv.y);
        }
    }
}

// ------------------------- BN helpers ---------------------------------------
__global__ void zero_kernel(float* __restrict__ p, int n) {
    int i = blockIdx.x*256 + threadIdx.x;
    if (i < n) p[i] = 0.f;
}

__global__ void colstats_kernel(const float* __restrict__ X, int N) {
    int c = blockIdx.x;
    __shared__ float r1[256], r2[256];
    float a = 0.f, b = 0.f;
    for (int r = threadIdx.x; r < Bn; r += 256) {
        float v = X[(size_t)r*N + c];
        a += v; b += v*v;
    }
    r1[threadIdx.x] = a; r2[threadIdx.x] = b; __syncthreads();
    for (int o = 128; o > 0; o >>= 1) {
        if (threadIdx.x < o) { r1[threadIdx.x] += r1[threadIdx.x+o]; r2[threadIdx.x] += r2[threadIdx.x+o]; }
        __syncthreads();
    }
    if (threadIdx.x == 0) {
        float m = r1[0] / (float)Bn;
        float var = r2[0] / (float)Bn - m*m;
        d_cm[c] = m;
        d_cis[c] = rsqrtf(var + EPSf);
    }
}

__global__ void normalize_kernel(const float* __restrict__ X, float* __restrict__ Y,
                                 int N, int ystride, int yoff) {
    int idx = blockIdx.x*256 + threadIdx.x;
    if (idx < Bn*N) {
        int r = idx / N, c = idx % N;
        Y[(size_t)r*ystride + yoff + c] = (X[idx] - d_cm[c]) * d_cis[c];
    }
}

// ------------------------- launch -------------------------------------------
extern "C" void kernel_launch(void* const* d_in, const int* in_sizes, int n_in,
                              void* d_out, int out_size) {
    const float* x      = (const float*)d_in[0];
    const float* lab    = (const float*)d_in[1];
    const float* fc1_w  = (const float*)d_in[2];
    const float* fc1_b  = (const float*)d_in[3];
    const float* q1     = (const float*)d_in[4];
    const float* fc3_w  = (const float*)d_in[5];
    const float* fc3_b  = (const float*)d_in[6];
    const float* q2     = (const float*)d_in[7];
    const float* fc5_w  = (const float*)d_in[8];
    const float* fc6_w  = (const float*)d_in[10];
    const float* fc7_w  = (const float*)d_in[12];
    const float* fc8_w  = (const float*)d_in[14];
    const float* fc8_b  = (const float*)d_in[15];
    const float* v      = (const float*)d_in[16];
    float* out = (float*)d_out;

    // device-global scratch addresses (host-visible pointers)
    float *ph, *ph5, *ph6p, *ph7p, *phcat, *pout8;
    cudaGetSymbolAddress((void**)&ph,    d_h);
    cudaGetSymbolAddress((void**)&ph5,   d_h5);
    cudaGetSymbolAddress((void**)&ph6p,  d_h6p);
    cudaGetSymbolAddress((void**)&ph7p,  d_h7p);
    cudaGetSymbolAddress((void**)&phcat, d_hcat);
    cudaGetSymbolAddress((void**)&pout8, d_out8);

    const int fc7_smem = (64*301 + 2*32*68) * 4 + 32*4;   // ~94.7 KB
    cudaFuncSetAttribute(fc7_kernel, cudaFuncAttributeMaxDynamicSharedMemorySize, fc7_smem);

    // prep: pairs + g, then W7gT = fc7_w^T * g (zero-padded)
    pair_kernel<<<(KPAD + 255)/256, 256>>>(v);
    w7g_kernel<<<dim3(KPAD/32, NOP/32), dim3(32, 32)>>>(fc7_w);

    // attention pooling
    attn_kernel<<<1184, 256>>>(x, fc1_w, fc1_b, q1, fc3_w, fc3_b, q2);
    attn_stats_kernel<<<dim3(Sn, 2), 256>>>(q1, q2);
    pool_kernel<<<Bn, 320>>>(x);

    // fc5 -> BN -> h5 (bias cancels under BN)
    gemm_kernel<<<dim3(5, Bn/64), 256>>>(ph, fc5_w, ph5, nullptr, En, 600);
    colstats_kernel<<<En, 256>>>(ph5, En);
    normalize_kernel<<<(Bn*En + 255)/256, 256>>>(ph5, ph5, En, En, 0);

    // fc6 (pre-BN) and fused cross-feature fc7 (pre-BN)
    gemm_kernel<<<dim3(5, Bn/64), 256>>>(ph5, fc6_w, ph6p, nullptr, En, En);
    zero_kernel<<<(Bn*En + 255)/256, 256>>>(ph7p, Bn*En);
    fc7_kernel<<<dim3(5, Bn/64, KSPLIT), 256, fc7_smem>>>();

    // BN both into the concat buffer
    colstats_kernel<<<En, 256>>>(ph6p, En);
    normalize_kernel<<<(Bn*En + 255)/256, 256>>>(ph6p, phcat, En, 600, 0);
    colstats_kernel<<<En, 256>>>(ph7p, En);
    normalize_kernel<<<(Bn*En + 255)/256, 256>>>(ph7p, phcat, En, 600, 300);

    // fc8 (+bias) and final label projection
    gemm_kernel<<<dim3(5, Bn/64), 256>>>(phcat, fc8_w, pout8, fc8_b, Un, 600);
    gemm_kernel<<<dim3(16, Bn/64), 256>>>(pout8, lab, out, nullptr, Ln, Un);
}

// round 7
// speedup vs baseline: 2.0659x; 2.0659x over previous
#include <cuda_runtime.h>
#include <cuda_bf16.h>
#include <math.h>
#include <stdint.h>

typedef unsigned long long ull;

#define Bn 2048
#define Sn 50
#define En 300
#define Cn 4
#define Un 300
#define Ln 1000
#define NPAIR 44850
#define EPSf  1e-5f
#define PADVAL (-4294967295.0f)

#define KPAD2 44928               /* 9 * 4992, mult of 32 */
#define KSPL 9
#define KCHUNK 4992
#define NS 156                    /* 4992/32 stages per CTA */
#define BHALF ((size_t)320 * KPAD2 * 2)   /* bytes of Bhi matrix */

// ------------------------- device scratch ------------------------------------
__device__ __align__(16) unsigned char d_Bsplit[2 * BHALF];  // 57.5MB bf16 hi+lo
__device__ unsigned int d_pairs[KPAD2];
__device__ float d_g[NPAIR];
__device__ float d_Aq [2][Bn*Sn];
__device__ float d_Asm[2][Bn*Sn];
__device__ float d_Asq[2][Bn*Sn];
__device__ float d_sgn[Bn*Sn];
__device__ float d_m [2][Sn];
__device__ float d_is[2][Sn];
__device__ float d_Q [2];
__device__ float d_h   [(size_t)Bn*600];
__device__ float d_h5  [(size_t)Bn*En];
__device__ float d_h5T [(size_t)En*Bn];
__device__ float d_h6p [(size_t)Bn*En];
__device__ float d_h7p [(size_t)Bn*En];
__device__ float d_hcat[(size_t)Bn*600];
__device__ float d_out8[(size_t)Bn*Un];
__device__ float d_cm[1024], d_cis[1024];

// ------------------------- PTX helpers ---------------------------------------
__device__ __forceinline__ uint32_t smem_u32(const void* p) {
    uint32_t a;
    asm("{ .reg .u64 t; cvta.to.shared.u64 t, %1; cvt.u32.u64 %0, t; }" : "=r"(a) : "l"(p));
    return a;
}
__device__ __forceinline__ void ldsm4(uint32_t* r, uint32_t addr) {
    asm volatile("ldmatrix.sync.aligned.m8n8.x4.shared.b16 {%0,%1,%2,%3}, [%4];"
        : "=r"(r[0]), "=r"(r[1]), "=r"(r[2]), "=r"(r[3]) : "r"(addr));
}
__device__ __forceinline__ void mma16816(float* d, const uint32_t* a, const uint32_t* b) {
    asm volatile("mma.sync.aligned.m16n8k16.row.col.f32.bf16.bf16.f32 "
        "{%0,%1,%2,%3}, {%4,%5,%6,%7}, {%8,%9}, {%0,%1,%2,%3};"
        : "+f"(d[0]), "+f"(d[1]), "+f"(d[2]), "+f"(d[3])
        : "r"(a[0]), "r"(a[1]), "r"(a[2]), "r"(a[3]), "r"(b[0]), "r"(b[1]));
}
__device__ __forceinline__ void cpa16(uint32_t dst, const void* src) {
    asm volatile("cp.async.cg.shared.global [%0], [%1], 16;" :: "r"(dst), "l"(src));
}
#define CP_COMMIT() asm volatile("cp.async.commit_group;" ::: "memory")
#define CP_WAIT0()  asm volatile("cp.async.wait_group 0;" ::: "memory")
#define CP_WAIT1()  asm volatile("cp.async.wait_group 1;" ::: "memory")

__device__ __forceinline__ ull pack2(float x, float y) {
    ull r; asm("mov.b64 %0, {%1,%2};" : "=l"(r) : "f"(x), "f"(y)); return r;
}
__device__ __forceinline__ float2 unpk(ull v) {
    float2 r; asm("mov.b64 {%0,%1}, %2;" : "=f"(r.x), "=f"(r.y) : "l"(v)); return r;
}
__device__ __forceinline__ void ffma2(ull &d, ull a, ull b) {
    asm("fma.rn.f32x2 %0, %1, %2, %0;" : "+l"(d) : "l"(a), "l"(b));
}
__device__ __forceinline__ uint32_t bfpack(float hi, float lo) {
    uint32_t r; asm("cvt.rn.bf16x2.f32 %0, %1, %2;" : "=r"(r) : "f"(hi), "f"(lo)); return r;
}

// ------------------------- pair indices + g ----------------------------------
__device__ __forceinline__ long long pair_off(long long i) { return i * (2LL*En - i - 1) / 2; }

__global__ void pair_kernel(const float* __restrict__ v) {
    int p = blockIdx.x * 256 + threadIdx.x;
    if (p >= KPAD2) return;
    if (p >= NPAIR) { d_pairs[p] = 0; return; }
    double a = 2.0*En - 1.0;
    int i = (int)((a - sqrt(a*a - 8.0*(double)p)) * 0.5);
    if (i < 0) i = 0; if (i > En-2) i = En-2;
    while (i > 0 && pair_off(i) > p) i--;
    while (i < En-2 && pair_off(i+1) <= p) i++;
    int j = i + 1 + (int)((long long)p - pair_off(i));
    d_pairs[p] = ((unsigned)i << 16) | (unsigned)j;
    float g = 0.f;
    #pragma unroll
    for (int c = 0; c < Cn; c++) g += v[i*Cn+c] * v[j*Cn+c];
    d_g[p] = g;
}

// B prep: Bhi/Blo[o][p] = bf16 hi/lo of fc7_w[o][p]*g[p]  (o<300 real, 300-319 = 0)
__global__ void w7bf_kernel(const float* __restrict__ fc7_w) {
    int o = blockIdx.y;
    int p = blockIdx.x * 256 + threadIdx.x;
    if (p >= KPAD2) return;
    float w = 0.f;
    if (o < En && p < NPAIR) w = fc7_w[(size_t)o*NPAIR + p] * d_g[p];
    uint32_t h = bfpack(0.f, w);        // low half = bf16(w)
    float hf = __uint_as_float(h << 16);
    uint32_t l = bfpack(0.f, w - hf);
    __nv_bfloat16* bhi = (__nv_bfloat16*)(d_Bsplit + (size_t)o*KPAD2*2);
    __nv_bfloat16* blo = (__nv_bfloat16*)(d_Bsplit + BHALF + (size_t)o*KPAD2*2);
    *(unsigned short*)&bhi[p] = (unsigned short)(h & 0xffff);
    *(unsigned short*)&blo[p] = (unsigned short)(l & 0xffff);
}

// ------------------------- attention pass 1 ----------------------------------
__global__ void attn_kernel(const float* __restrict__ x,
                            const float* __restrict__ w1, const float* __restrict__ b1,
                            const float* __restrict__ q1,
                            const float* __restrict__ w3, const float* __restrict__ b3,
                            const float* __restrict__ q3) {
    __shared__ float ws[16*En];
    __shared__ float bs[16], qs[16];
    int tid = threadIdx.x;
    for (int idx = tid; idx < 16*En; idx += blockDim.x) {
        int t = idx / En, e = idx % En;
        ws[idx] = (t < 8) ? w1[t*En + e] : w3[(t-8)*En + e];
    }
    if (tid < 8)       { bs[tid] = b1[tid];   qs[tid] = q1[tid]; }
    else if (tid < 16) { bs[tid] = b3[tid-8]; qs[tid] = q3[tid-8]; }
    __syncthreads();
    int lane = tid & 31;
    int gw = blockIdx.x * (blockDim.x >> 5) + (tid >> 5);
    int nw = gridDim.x * (blockDim.x >> 5);
    for (int item = gw; item < Bn*Sn; item += nw) {
        const float* xp = x + (size_t)item * En;
        float dot[16];
        #pragma unroll
        for (int t = 0; t < 16; t++) dot[t] = 0.f;
        float ab = 0.f;
        for (int e = lane; e < En; e += 32) {
            float xv = xp[e];
            ab += fabsf(xv);
            #pragma unroll
            for (int t = 0; t < 16; t++) dot[t] += xv * ws[t*En + e];
        }
        #pragma unroll
        for (int o = 16; o > 0; o >>= 1) {
            ab += __shfl_down_sync(0xffffffffu, ab, o);
            #pragma unroll
            for (int t = 0; t < 16; t++) dot[t] += __shfl_down_sync(0xffffffffu, dot[t], o);
        }
        if (lane == 0) {
            #pragma unroll
            for (int h = 0; h < 2; h++) {
                float asum = 0.f, asq = 0.f, aq = 0.f;
                #pragma unroll
                for (int t = 0; t < 8; t++) {
                    float av = dot[h*8+t] + bs[h*8+t];
                    av = av > 0.f ? av : 0.f;
                    asum += av; asq += av*av; aq += av * qs[h*8+t];
                }
                d_Aq[h][item] = aq; d_Asm[h][item] = asum; d_Asq[h][item] = asq;
            }
            d_sgn[item] = ab;
        }
    }
}

__global__ void attn_stats_kernel(const float* __restrict__ q1, const float* __restrict__ q3) {
    int s = blockIdx.x, h = blockIdx.y;
    __shared__ float r1[256], r2[256];
    float a = 0.f, b = 0.f;
    for (int bb = threadIdx.x; bb < Bn; bb += 256) {
        a += d_Asm[h][bb*Sn + s];
        b += d_Asq[h][bb*Sn + s];
    }
    r1[threadIdx.x] = a; r2[threadIdx.x] = b; __syncthreads();
    for (int o = 128; o > 0; o >>= 1) {
        if (threadIdx.x < o) { r1[threadIdx.x] += r1[threadIdx.x+o]; r2[threadIdx.x] += r2[threadIdx.x+o]; }
        __syncthreads();
    }
    if (threadIdx.x == 0) {
        float n = (float)(Bn * 8);
        float m = r1[0] / n;
        float var = r2[0] / n - m*m;
        d_m[h][s] = m;
        d_is[h][s] = rsqrtf(var + EPSf);
        if (s == 0) {
            const float* q = h ? q3 : q1;
            float Q = 0.f;
            for (int t = 0; t < 8; t++) Q += q[t];
            d_Q[h] = Q;
        }
    }
}

__global__ void pool_kernel(const float* __restrict__ x) {
    int b = blockIdx.x;
    __shared__ float w0[Sn], w1s[Sn];
    int tid = threadIdx.x;
    if (tid < Sn) {
        int item = b*Sn + tid;
        float sg = d_sgn[item];
        float s0 = (sg == 0.f) ? PADVAL : (d_Aq[0][item] - d_m[0][tid]*d_Q[0]) * d_is[0][tid];
        float s1 = (sg == 0.f) ? PADVAL : (d_Aq[1][item] - d_m[1][tid]*d_Q[1]) * d_is[1][tid];
        w0[tid] = s0; w1s[tid] = s1;
    }
    __syncthreads();
    float mx0 = -INFINITY, mx1 = -INFINITY;
    for (int s = 0; s < Sn; s++) { mx0 = fmaxf(mx0, w0[s]); mx1 = fmaxf(mx1, w1s[s]); }
    __syncthreads();
    if (tid < Sn) { w0[tid] = expf(w0[tid]-mx0); w1s[tid] = expf(w1s[tid]-mx1); }
    __syncthreads();
    float sm0 = 0.f, sm1 = 0.f;
    for (int s = 0; s < Sn; s++) { sm0 += w0[s]; sm1 += w1s[s]; }
    float inv0 = 1.f/sm0, inv1 = 1.f/sm1;
    if (tid < En) {
        float a0 = 0.f, a1 = 0.f;
        const float* xp = x + (size_t)b*Sn*En + tid;
        for (int s = 0; s < Sn; s++) {
            float xv = xp[(size_t)s*En];
            a0 += w0[s]*xv; a1 += w1s[s]*xv;
        }
        d_h[(size_t)b*600 + tid]       = a0*inv0;
        d_h[(size_t)b*600 + 300 + tid] = a1*inv1;
    }
}

// ------------------------- small SGEMM (f32x2) --------------------------------
__global__ void gemm_kernel(const float* __restrict__ A, const float* __restrict__ W,
                            float* __restrict__ Cout, const float* __restrict__ bias,
                            int N, int K) {
    __shared__ float As[12*68];
    __shared__ float Ws[12*68];
    int m0 = blockIdx.y * 64, n0 = blockIdx.x * 64;
    int tid = threadIdx.x;
    int ty = tid >> 4, tx = tid & 15;
    ull acc[4][2];
    #pragma unroll
    for (int i = 0; i < 4; i++) { acc[i][0] = 0ULL; acc[i][1] = 0ULL; }
    for (int kc = 0; kc < K; kc += 12) {
        for (int idx = tid; idx < 64*12; idx += 256) {
            int r = idx / 12, kk = idx % 12;
            As[kk*68 + r] = A[(size_t)(m0+r)*K + kc + kk];
        }
        for (int idx = tid; idx < 64*12; idx += 256) {
            int c = idx / 12, kk = idx % 12;
            int col = n0 + c;
            Ws[kk*68 + c] = (col < N) ? W[(size_t)col*K + kc + kk] : 0.f;
        }
        __syncthreads();
        #pragma unroll
        for (int kk = 0; kk < 12; kk++) {
            float4 av = *(const float4*)&As[kk*68 + ty*4];
            float4 bv = *(const float4*)&Ws[kk*68 + tx*4];
            ull b01 = pack2(bv.x, bv.y), b23 = pack2(bv.z, bv.w);
            ull a;
            a = pack2(av.x, av.x); ffma2(acc[0][0], a, b01); ffma2(acc[0][1], a, b23);
            a = pack2(av.y, av.y); ffma2(acc[1][0], a, b01); ffma2(acc[1][1], a, b23);
            a = pack2(av.z, av.z); ffma2(acc[2][0], a, b01); ffma2(acc[2][1], a, b23);
            a = pack2(av.w, av.w); ffma2(acc[3][0], a, b01); ffma2(acc[3][1], a, b23);
        }
        __syncthreads();
    }
    #pragma unroll
    for (int i = 0; i < 4; i++) {
        int row = m0 + ty*4 + i;
        #pragma unroll
        for (int jj = 0; jj < 2; jj++) {
            float2 vv = unpk(acc[i][jj]);
            int col = n0 + tx*4 + jj*2;
            if (col < N)     Cout[(size_t)row*N + col]     = vv.x + (bias ? bias[col]   : 0.f);
            if (col + 1 < N) Cout[(size_t)row*N + col + 1] = vv.y + (bias ? bias[col+1] : 0.f);
        }
    }
}

// ------------------------- h5 transpose ---------------------------------------
__global__ void h5t_kernel() {
    __shared__ float t[32][33];
    int b0 = blockIdx.x*32, e0 = blockIdx.y*32;
    int tx = threadIdx.x, ty = threadIdx.y;
    if (e0 + tx < En) t[ty][tx] = d_h5[(size_t)(b0+ty)*En + e0+tx];
    __syncthreads();
    if (e0 + ty < En) d_h5T[(size_t)(e0+ty)*Bn + b0+tx] = t[tx][ty];
}

// ------------------------- fc7 MMA GEMM ---------------------------------------
// C[64 x 320] per CTA; A = cross(h5) bf16 hi/lo on the fly; B pre-split.
// SMEM: h5 tile [300][68] f32 (81600B) | A 2x(hi 5120 + lo 5120) | B 2x(hi 25600 + lo 25600)
#define H5OFF 0
#define AOFF 81600
#define BOFF 102080
#define FC7_SMEM 204480

__global__ void __launch_bounds__(256, 1) fc7_mma() {
    extern __shared__ char sm[];
    float* h5s = (float*)(sm + H5OFF);
    int tid = threadIdx.x, lane = tid & 31, wid = tid >> 5;
    int m0 = blockIdx.x * 64;
    int ck0 = blockIdx.y * KCHUNK;
    int m_off = (wid & 1) * 32;
    int n_off = (wid >> 1) * 80;

    // h5 tile load: h5s[e][r] = h5T[e][m0+r]
    for (int idx = tid; idx < En*64; idx += 256) {
        int e = idx >> 6, r = idx & 63;
        h5s[e*68 + r] = d_h5T[(size_t)e*Bn + m0 + r];
    }

    uint32_t sA = smem_u32(sm + AOFF);
    uint32_t sB = smem_u32(sm + BOFF);

    // ldmatrix lane offsets
    int ar = (lane & 7) + ((lane >> 3) & 1) * 8;
    int ak = (lane >> 4) * 16;
    int offA0 = (m_off + ar) * 80 + ak;
    int offA1 = (m_off + 16 + ar) * 80 + ak;
    int bn = (lane & 7) + (lane >> 4) * 8;
    int bk = ((lane >> 3) & 1) * 16;
    int offB = bn * 80 + bk;

    // gen invariants
    int kp = tid & 15;
    int r0 = (tid >> 4) * 4;

    float acc[2][10][4];
    #pragma unroll
    for (int a = 0; a < 2; a++)
        #pragma unroll
        for (int b = 0; b < 10; b++)
            #pragma unroll
            for (int c = 0; c < 4; c++) acc[a][b][c] = 0.f;

    __syncthreads();   // h5s ready

    const char* srcB = (const char*)d_Bsplit + (size_t)ck0 * 2;

    // ---- stage 0: B cp.async + A gen ----
    {
        #pragma unroll
        for (int it = 0; it < 5; it++) {
            int idx = tid + it*256;
            int o = idx >> 2, c = idx & 3;
            cpa16(sB + o*80 + c*16, srcB + (size_t)o*(KPAD2*2) + c*16);
            cpa16(sB + 25600 + o*80 + c*16, srcB + BHALF + (size_t)o*(KPAD2*2) + c*16);
        }
        CP_COMMIT();
        int kg = ck0 + 2*kp;
        uint2 pr = *(const uint2*)&d_pairs[kg];
        int i0 = pr.x >> 16, j0 = pr.x & 0xffff, i1 = pr.y >> 16, j1 = pr.y & 0xffff;
        float4 A0 = *(const float4*)&h5s[i0*68 + r0];
        float4 B0 = *(const float4*)&h5s[j0*68 + r0];
        float4 A1 = *(const float4*)&h5s[i1*68 + r0];
        float4 B1 = *(const float4*)&h5s[j1*68 + r0];
        float p0[4] = {A0.x*B0.x, A0.y*B0.y, A0.z*B0.z, A0.w*B0.w};
        float p1[4] = {A1.x*B1.x, A1.y*B1.y, A1.z*B1.z, A1.w*B1.w};
        char* hi = sm + AOFF; char* lo = hi + 5120;
        #pragma unroll
        for (int r = 0; r < 4; r++) {
            uint32_t h = bfpack(p1[r], p0[r]);
            float l0 = p0[r] - __uint_as_float(h << 16);
            float l1 = p1[r] - __uint_as_float(h & 0xffff0000u);
            *(uint32_t*)(hi + (r0+r)*80 + kp*4) = h;
            *(uint32_t*)(lo + (r0+r)*80 + kp*4) = bfpack(l1, l0);
        }
    }

    for (int s = 0; s < NS; s++) {
        int sp = s & 1;
        if (s + 1 < NS) {
            // prefetch B(s+1) into other buffer
            uint32_t dB = sB + (sp^1)*51200;
            const char* sc = srcB + (size_t)(s+1)*64;
            #pragma unroll
            for (int it = 0; it < 5; it++) {
                int idx = tid + it*256;
                int o = idx >> 2, c = idx & 3;
                cpa16(dB + o*80 + c*16, sc + (size_t)o*(KPAD2*2) + c*16);
                cpa16(dB + 25600 + o*80 + c*16, sc + BHALF + (size_t)o*(KPAD2*2) + c*16);
            }
            CP_COMMIT();
            CP_WAIT1();
        } else {
            CP_WAIT0();
        }
        __syncthreads();   // stage s A + B visible

        // ---- MMA over stage s ----
        uint32_t aH = sA + sp*10240, aL = aH + 5120;
        uint32_t bH = sB + sp*51200, bL = bH + 25600;
        #pragma unroll
        for (int kh = 0; kh < 2; kh++) {
            int kb = kh * 32;
            uint32_t ah0[4], ah1[4], al0[4], al1[4];
            ldsm4(ah0, aH + offA0 + kb); ldsm4(ah1, aH + offA1 + kb);
            ldsm4(al0, aL + offA0 + kb); ldsm4(al1, aL + offA1 + kb);
            #pragma unroll
            for (int gi = 0; gi < 5; gi++) {
                uint32_t bh[4], bl[4];
                uint32_t ob = (uint32_t)((n_off + gi*16)*80 + offB + kb);
                ldsm4(bh, bH + ob); ldsm4(bl, bL + ob);
                mma16816(acc[0][gi*2],   ah0, bh);
                mma16816(acc[0][gi*2+1], ah0, bh+2);
                mma16816(acc[1][gi*2],   ah1, bh);
                mma16816(acc[1][gi*2+1], ah1, bh+2);
                mma16816(acc[0][gi*2],   ah0, bl);
                mma16816(acc[0][gi*2+1], ah0, bl+2);
                mma16816(acc[1][gi*2],   ah1, bl);
                mma16816(acc[1][gi*2+1], ah1, bl+2);
                mma16816(acc[0][gi*2],   al0, bh);
                mma16816(acc[0][gi*2+1], al0, bh+2);
                mma16816(acc[1][gi*2],   al1, bh);
                mma16816(acc[1][gi*2+1], al1, bh+2);
            }
        }

        // ---- gen A(s+1) into other buffer ----
        if (s + 1 < NS) {
            int kg = ck0 + (s+1)*32 + 2*kp;
            uint2 pr = *(const uint2*)&d_pairs[kg];
            int i0 = pr.x >> 16, j0 = pr.x & 0xffff, i1 = pr.y >> 16, j1 = pr.y & 0xffff;
            float4 A0 = *(const float4*)&h5s[i0*68 + r0];
            float4 B0 = *(const float4*)&h5s[j0*68 + r0];
            float4 A1 = *(const float4*)&h5s[i1*68 + r0];
            float4 B1 = *(const float4*)&h5s[j1*68 + r0];
            float p0[4] = {A0.x*B0.x, A0.y*B0.y, A0.z*B0.z, A0.w*B0.w};
            float p1[4] = {A1.x*B1.x, A1.y*B1.y, A1.z*B1.z, A1.w*B1.w};
            char* hi = sm + AOFF + (sp^1)*10240; char* lo = hi + 5120;
            #pragma unroll
            for (int r = 0; r < 4; r++) {
                uint32_t h = bfpack(p1[r], p0[r]);
                float l0 = p0[r] - __uint_as_float(h << 16);
                float l1 = p1[r] - __uint_as_float(h & 0xffff0000u);
                *(uint32_t*)(hi + (r0+r)*80 + kp*4) = h;
                *(uint32_t*)(lo + (r0+r)*80 + kp*4) = bfpack(l1, l0);
            }
        }
        __syncthreads();   // protect buffer sp from next prefetch until all read
    }

    // ---- epilogue ----
    int tr = lane >> 2, tc = (lane & 3) * 2;
    #pragma unroll
    for (int mt = 0; mt < 2; mt++) {
        #pragma unroll
        for (int nt = 0; nt < 10; nt++) {
            int row = m0 + m_off + mt*16 + tr;
            int col = n_off + nt*8 + tc;
            float* a = acc[mt][nt];
            if (col < En) {
                atomicAdd(&d_h7p[(size_t)row*En + col], a[0]);
                atomicAdd(&d_h7p[(size_t)(row+8)*En + col], a[2]);
            }
            if (col + 1 < En) {
                atomicAdd(&d_h7p[(size_t)row*En + col + 1], a[1]);
                atomicAdd(&d_h7p[(size_t)(row+8)*En + col + 1], a[3]);
            }
        }
    }
}

// ------------------------- BN helpers -----------------------------------------
__global__ void zero_kernel(float* __restrict__ p, int n) {
    int i = blockIdx.x*256 + threadIdx.x;
    if (i < n) p[i] = 0.f;
}

__global__ void colstats_kernel(const float* __restrict__ X, int N) {
    int c = blockIdx.x;
    __shared__ float r1[256], r2[256];
    float a = 0.f, b = 0.f;
    for (int r = threadIdx.x; r < Bn; r += 256) {
        float v = X[(size_t)r*N + c];
        a += v; b += v*v;
    }
    r1[threadIdx.x] = a; r2[threadIdx.x] = b; __syncthreads();
    for (int o = 128; o > 0; o >>= 1) {
        if (threadIdx.x < o) { r1[threadIdx.x] += r1[threadIdx.x+o]; r2[threadIdx.x] += r2[threadIdx.x+o]; }
        __syncthreads();
    }
    if (threadIdx.x == 0) {
        float m = r1[0] / (float)Bn;
        float var = r2[0] / (float)Bn - m*m;
        d_cm[c] = m;
        d_cis[c] = rsqrtf(var + EPSf);
    }
}

__global__ void normalize_kernel(const float* __restrict__ X, float* __restrict__ Y,
                                 int N, int ystride, int yoff) {
    int idx = blockIdx.x*256 + threadIdx.x;
    if (idx < Bn*N) {
        int r = idx / N, c = idx % N;
        Y[(size_t)r*ystride + yoff + c] = (X[idx] - d_cm[c]) * d_cis[c];
    }
}

// ------------------------- launch ----------------------------------------------
extern "C" void kernel_launch(void* const* d_in, const int* in_sizes, int n_in,
                              void* d_out, int out_size) {
    const float* x      = (const float*)d_in[0];
    const float* lab    = (const float*)d_in[1];
    const float* fc1_w  = (const float*)d_in[2];
    const float* fc1_b  = (const float*)d_in[3];
    const float* q1     = (const float*)d_in[4];
    const float* fc3_w  = (const float*)d_in[5];
    const float* fc3_b  = (const float*)d_in[6];
    const float* q2     = (const float*)d_in[7];
    const float* fc5_w  = (const float*)d_in[8];
    const float* fc6_w  = (const float*)d_in[10];
    const float* fc7_w  = (const float*)d_in[12];
    const float* fc8_w  = (const float*)d_in[14];
    const float* fc8_b  = (const float*)d_in[15];
    const float* v      = (const float*)d_in[16];
    float* out = (float*)d_out;

    float *ph, *ph5, *ph6p, *ph7p, *phcat, *pout8;
    cudaGetSymbolAddress((void**)&ph,    d_h);
    cudaGetSymbolAddress((void**)&ph5,   d_h5);
    cudaGetSymbolAddress((void**)&ph6p,  d_h6p);
    cudaGetSymbolAddress((void**)&ph7p,  d_h7p);
    cudaGetSymbolAddress((void**)&phcat, d_hcat);
    cudaGetSymbolAddress((void**)&pout8, d_out8);

    cudaFuncSetAttribute(fc7_mma, cudaFuncAttributeMaxDynamicSharedMemorySize, FC7_SMEM);

    pair_kernel<<<(KPAD2 + 255)/256, 256>>>(v);
    w7bf_kernel<<<dim3((KPAD2 + 255)/256, 320), 256>>>(fc7_w);

    attn_kernel<<<1184, 256>>>(x, fc1_w, fc1_b, q1, fc3_w, fc3_b, q2);
    attn_stats_kernel<<<dim3(Sn, 2), 256>>>(q1, q2);
    pool_kernel<<<Bn, 320>>>(x);

    gemm_kernel<<<dim3(5, Bn/64), 256>>>(ph, fc5_w, ph5, nullptr, En, 600);
    colstats_kernel<<<En, 256>>>(ph5, En);
    normalize_kernel<<<(Bn*En + 255)/256, 256>>>(ph5, ph5, En, En, 0);
    h5t_kernel<<<dim3(Bn/32, (En+31)/32), dim3(32, 32)>>>();

    gemm_kernel<<<dim3(5, Bn/64), 256>>>(ph5, fc6_w, ph6p, nullptr, En, En);
    zero_kernel<<<(Bn*En + 255)/256, 256>>>(ph7p, Bn*En);
    fc7_mma<<<dim3(Bn/64, KSPL), 256, FC7_SMEM>>>();

    colstats_kernel<<<En, 256>>>(ph6p, En);
    normalize_kernel<<<(Bn*En + 255)/256, 256>>>(ph6p, phcat, En, 600, 0);
    colstats_kernel<<<En, 256>>>(ph7p, En);
    normalize_kernel<<<(Bn*En + 255)/256, 256>>>(ph7p, phcat, En, 600, 300);

    gemm_kernel<<<dim3(5, Bn/64), 256>>>(phcat, fc8_w, pout8, fc8_b, Un, 600);
    gemm_kernel<<<dim3(16, Bn/64), 256>>>(pout8, lab, out, nullptr, Ln, Un);
}

// round 10
// speedup vs baseline: 2.1235x; 1.0279x over previous
#include <cuda_runtime.h>
#include <cuda_bf16.h>
#include <math.h>
#include <stdint.h>

typedef unsigned long long ull;

#define Bn 2048
#define Sn 50
#define En 300
#define Cn 4
#define Un 300
#define Ln 1000
#define NPAIR 44850
#define EPSf  1e-5f
#define PADVAL (-4294967295.0f)

#define KPAD2 44928               /* 9 * 4992, mult of 32 */
#define KSPL 9
#define KCHUNK 4992
#define NS 156                    /* 4992/32 stages per CTA */
#define BHALF ((size_t)320 * KPAD2 * 2)   /* bytes of Bhi matrix */

// ------------------------- device scratch ------------------------------------
__device__ __align__(16) unsigned char d_Bsplit[2 * BHALF];  // 57.5MB bf16 hi+lo
__device__ __align__(16) unsigned int d_pairs[KPAD2];
__device__ float d_g[NPAIR];
__device__ float d_Aq [2][Bn*Sn];
__device__ float d_Asm[2][Bn*Sn];
__device__ float d_Asq[2][Bn*Sn];
__device__ float d_sgn[Bn*Sn];
__device__ float d_m [2][Sn];
__device__ float d_is[2][Sn];
__device__ float d_Q [2];
__device__ __align__(16) float d_h   [(size_t)Bn*600];
__device__ __align__(16) float d_h5  [(size_t)Bn*En];
__device__ __align__(16) float d_h5T [(size_t)En*Bn];
__device__ __align__(16) float d_h6p [(size_t)Bn*En];
__device__ __align__(16) float d_h7p [(size_t)Bn*En];
__device__ __align__(16) float d_hcat[(size_t)Bn*600];
__device__ __align__(16) float d_out8[(size_t)Bn*Un];

// ------------------------- PTX helpers ---------------------------------------
__device__ __forceinline__ uint32_t smem_u32(const void* p) {
    uint32_t a;
    asm("{ .reg .u64 t; cvta.to.shared.u64 t, %1; cvt.u32.u64 %0, t; }" : "=r"(a) : "l"(p));
    return a;
}
__device__ __forceinline__ void ldsm4(uint32_t* r, uint32_t addr) {
    asm volatile("ldmatrix.sync.aligned.m8n8.x4.shared.b16 {%0,%1,%2,%3}, [%4];"
        : "=r"(r[0]), "=r"(r[1]), "=r"(r[2]), "=r"(r[3]) : "r"(addr));
}
__device__ __forceinline__ void mma16816(float* d, const uint32_t* a, const uint32_t* b) {
    asm volatile("mma.sync.aligned.m16n8k16.row.col.f32.bf16.bf16.f32 "
        "{%0,%1,%2,%3}, {%4,%5,%6,%7}, {%8,%9}, {%0,%1,%2,%3};"
        : "+f"(d[0]), "+f"(d[1]), "+f"(d[2]), "+f"(d[3])
        : "r"(a[0]), "r"(a[1]), "r"(a[2]), "r"(a[3]), "r"(b[0]), "r"(b[1]));
}
__device__ __forceinline__ void cpa16(uint32_t dst, const void* src) {
    asm volatile("cp.async.cg.shared.global [%0], [%1], 16;" :: "r"(dst), "l"(src));
}
#define CP_COMMIT() asm volatile("cp.async.commit_group;" ::: "memory")
#define CP_WAIT0()  asm volatile("cp.async.wait_group 0;" ::: "memory")
#define CP_WAIT1()  asm volatile("cp.async.wait_group 1;" ::: "memory")

__device__ __forceinline__ ull pack2(float x, float y) {
    ull r; asm("mov.b64 %0, {%1,%2};" : "=l"(r) : "f"(x), "f"(y)); return r;
}
__device__ __forceinline__ float2 unpk(ull v) {
    float2 r; asm("mov.b64 {%0,%1}, %2;" : "=f"(r.x), "=f"(r.y) : "l"(v)); return r;
}
__device__ __forceinline__ void ffma2(ull &d, ull a, ull b) {
    asm("fma.rn.f32x2 %0, %1, %2, %0;" : "+l"(d) : "l"(a), "l"(b));
}
__device__ __forceinline__ uint32_t bfpack(float hi, float lo) {
    uint32_t r; asm("cvt.rn.bf16x2.f32 %0, %1, %2;" : "=r"(r) : "f"(hi), "f"(lo)); return r;
}

// ------------------------- pair indices + g ----------------------------------
__device__ __forceinline__ long long pair_off(long long i) { return i * (2LL*En - i - 1) / 2; }

__global__ void pair_kernel(const float* __restrict__ v) {
    int p = blockIdx.x * 256 + threadIdx.x;
    if (p >= KPAD2) return;
    if (p >= NPAIR) { d_pairs[p] = 0; return; }
    double a = 2.0*En - 1.0;
    int i = (int)((a - sqrt(a*a - 8.0*(double)p)) * 0.5);
    if (i < 0) i = 0; if (i > En-2) i = En-2;
    while (i > 0 && pair_off(i) > p) i--;
    while (i < En-2 && pair_off(i+1) <= p) i++;
    int j = i + 1 + (int)((long long)p - pair_off(i));
    d_pairs[p] = ((unsigned)i << 16) | (unsigned)j;
    float g = 0.f;
    #pragma unroll
    for (int c = 0; c < Cn; c++) g += v[i*Cn+c] * v[j*Cn+c];
    d_g[p] = g;
}

// B prep: Bhi/Blo[o][p] = bf16 hi/lo of fc7_w[o][p]*g[p]
__global__ void w7bf_kernel(const float* __restrict__ fc7_w) {
    int o = blockIdx.y;
    int p = blockIdx.x * 256 + threadIdx.x;
    if (p >= KPAD2) return;
    float w = 0.f;
    if (o < En && p < NPAIR) w = fc7_w[(size_t)o*NPAIR + p] * d_g[p];
    uint32_t h = bfpack(0.f, w);
    float hf = __uint_as_float(h << 16);
    uint32_t l = bfpack(0.f, w - hf);
    __nv_bfloat16* bhi = (__nv_bfloat16*)(d_Bsplit + (size_t)o*KPAD2*2);
    __nv_bfloat16* blo = (__nv_bfloat16*)(d_Bsplit + BHALF + (size_t)o*KPAD2*2);
    *(unsigned short*)&bhi[p] = (unsigned short)(h & 0xffff);
    *(unsigned short*)&blo[p] = (unsigned short)(l & 0xffff);
}

// ------------------------- attention pass 1 ----------------------------------
// wsT[e][20]: 16 used; stride 80B keeps LDS.128 conflict-free and 16B-aligned.
__global__ void attn_kernel(const float* __restrict__ x,
                            const float* __restrict__ w1, const float* __restrict__ b1,
                            const float* __restrict__ q1,
                            const float* __restrict__ w3, const float* __restrict__ b3,
                            const float* __restrict__ q3) {
    __shared__ float wsT[En*20];
    __shared__ float bs[16], qs[16];
    int tid = threadIdx.x;
    for (int idx = tid; idx < 16*En; idx += blockDim.x) {
        int t = idx / En, e = idx % En;
        float val = (t < 8) ? w1[t*En + e] : w3[(t-8)*En + e];
        wsT[e*20 + t] = val;
    }
    if (tid < 8)       { bs[tid] = b1[tid];   qs[tid] = q1[tid]; }
    else if (tid < 16) { bs[tid] = b3[tid-8]; qs[tid] = q3[tid-8]; }
    __syncthreads();
    int lane = tid & 31;
    int gw = blockIdx.x * (blockDim.x >> 5) + (tid >> 5);
    int nw = gridDim.x * (blockDim.x >> 5);
    for (int item = gw; item < Bn*Sn; item += nw) {
        const float* xp = x + (size_t)item * En;
        float dot[16];
        #pragma unroll
        for (int t = 0; t < 16; t++) dot[t] = 0.f;
        float ab = 0.f;
        for (int e = lane; e < En; e += 32) {
            float xv = xp[e];
            ab += fabsf(xv);
            const float4* wp = (const float4*)&wsT[e*20];
            float4 wa = wp[0], wb = wp[1], wc = wp[2], wd = wp[3];
            dot[0]  += xv*wa.x; dot[1]  += xv*wa.y; dot[2]  += xv*wa.z; dot[3]  += xv*wa.w;
            dot[4]  += xv*wb.x; dot[5]  += xv*wb.y; dot[6]  += xv*wb.z; dot[7]  += xv*wb.w;
            dot[8]  += xv*wc.x; dot[9]  += xv*wc.y; dot[10] += xv*wc.z; dot[11] += xv*wc.w;
            dot[12] += xv*wd.x; dot[13] += xv*wd.y; dot[14] += xv*wd.z; dot[15] += xv*wd.w;
        }
        #pragma unroll
        for (int o = 16; o > 0; o >>= 1) {
            ab += __shfl_down_sync(0xffffffffu, ab, o);
            #pragma unroll
            for (int t = 0; t < 16; t++) dot[t] += __shfl_down_sync(0xffffffffu, dot[t], o);
        }
        if (lane == 0) {
            #pragma unroll
            for (int h = 0; h < 2; h++) {
                float asum = 0.f, asq = 0.f, aq = 0.f;
                #pragma unroll
                for (int t = 0; t < 8; t++) {
                    float av = dot[h*8+t] + bs[h*8+t];
                    av = av > 0.f ? av : 0.f;
                    asum += av; asq += av*av; aq += av * qs[h*8+t];
                }
                d_Aq[h][item] = aq; d_Asm[h][item] = asum; d_Asq[h][item] = asq;
            }
            d_sgn[item] = ab;
        }
    }
}

__global__ void attn_stats_kernel(const float* __restrict__ q1, const float* __restrict__ q3) {
    int s = blockIdx.x, h = blockIdx.y;
    __shared__ float r1[256], r2[256];
    float a = 0.f, b = 0.f;
    for (int bb = threadIdx.x; bb < Bn; bb += 256) {
        a += d_Asm[h][bb*Sn + s];
        b += d_Asq[h][bb*Sn + s];
    }
    r1[threadIdx.x] = a; r2[threadIdx.x] = b; __syncthreads();
    for (int o = 128; o > 0; o >>= 1) {
        if (threadIdx.x < o) { r1[threadIdx.x] += r1[threadIdx.x+o]; r2[threadIdx.x] += r2[threadIdx.x+o]; }
        __syncthreads();
    }
    if (threadIdx.x == 0) {
        float n = (float)(Bn * 8);
        float m = r1[0] / n;
        float var = r2[0] / n - m*m;
        d_m[h][s] = m;
        d_is[h][s] = rsqrtf(var + EPSf);
        if (s == 0) {
            const float* q = h ? q3 : q1;
            float Q = 0.f;
            for (int t = 0; t < 8; t++) Q += q[t];
            d_Q[h] = Q;
        }
    }
}

__global__ void pool_kernel(const float* __restrict__ x) {
    int b = blockIdx.x;
    __shared__ float w0[Sn], w1s[Sn];
    int tid = threadIdx.x;
    if (tid < Sn) {
        int item = b*Sn + tid;
        float sg = d_sgn[item];
        float s0 = (sg == 0.f) ? PADVAL : (d_Aq[0][item] - d_m[0][tid]*d_Q[0]) * d_is[0][tid];
        float s1 = (sg == 0.f) ? PADVAL : (d_Aq[1][item] - d_m[1][tid]*d_Q[1]) * d_is[1][tid];
        w0[tid] = s0; w1s[tid] = s1;
    }
    __syncthreads();
    float mx0 = -INFINITY, mx1 = -INFINITY;
    for (int s = 0; s < Sn; s++) { mx0 = fmaxf(mx0, w0[s]); mx1 = fmaxf(mx1, w1s[s]); }
    __syncthreads();
    if (tid < Sn) { w0[tid] = expf(w0[tid]-mx0); w1s[tid] = expf(w1s[tid]-mx1); }
    __syncthreads();
    float sm0 = 0.f, sm1 = 0.f;
    for (int s = 0; s < Sn; s++) { sm0 += w0[s]; sm1 += w1s[s]; }
    float inv0 = 1.f/sm0, inv1 = 1.f/sm1;
    if (tid < En) {
        float a0 = 0.f, a1 = 0.f;
        const float* xp = x + (size_t)b*Sn*En + tid;
        for (int s = 0; s < Sn; s++) {
            float xv = xp[(size_t)s*En];
            a0 += w0[s]*xv; a1 += w1s[s]*xv;
        }
        d_h[(size_t)b*600 + tid]       = a0*inv0;
        d_h[(size_t)b*600 + 300 + tid] = a1*inv1;
    }
}

// ------------------------- small SGEMM (f32x2) --------------------------------
__global__ void gemm_kernel(const float* __restrict__ A, const float* __restrict__ W,
                            float* __restrict__ Cout, const float* __restrict__ bias,
                            int N, int K) {
    __shared__ float As[12*68];
    __shared__ float Ws[12*68];
    int m0 = blockIdx.y * 64, n0 = blockIdx.x * 64;
    int tid = threadIdx.x;
    int ty = tid >> 4, tx = tid & 15;
    ull acc[4][2];
    #pragma unroll
    for (int i = 0; i < 4; i++) { acc[i][0] = 0ULL; acc[i][1] = 0ULL; }
    for (int kc = 0; kc < K; kc += 12) {
        for (int idx = tid; idx < 64*12; idx += 256) {
            int r = idx / 12, kk = idx % 12;
            As[kk*68 + r] = A[(size_t)(m0+r)*K + kc + kk];
        }
        for (int idx = tid; idx < 64*12; idx += 256) {
            int c = idx / 12, kk = idx % 12;
            int col = n0 + c;
            Ws[kk*68 + c] = (col < N) ? W[(size_t)col*K + kc + kk] : 0.f;
        }
        __syncthreads();
        #pragma unroll
        for (int kk = 0; kk < 12; kk++) {
            float4 av = *(const float4*)&As[kk*68 + ty*4];
            float4 bv = *(const float4*)&Ws[kk*68 + tx*4];
            ull b01 = pack2(bv.x, bv.y), b23 = pack2(bv.z, bv.w);
            ull a;
            a = pack2(av.x, av.x); ffma2(acc[0][0], a, b01); ffma2(acc[0][1], a, b23);
            a = pack2(av.y, av.y); ffma2(acc[1][0], a, b01); ffma2(acc[1][1], a, b23);
            a = pack2(av.z, av.z); ffma2(acc[2][0], a, b01); ffma2(acc[2][1], a, b23);
            a = pack2(av.w, av.w); ffma2(acc[3][0], a, b01); ffma2(acc[3][1], a, b23);
        }
        __syncthreads();
    }
    #pragma unroll
    for (int i = 0; i < 4; i++) {
        int row = m0 + ty*4 + i;
        #pragma unroll
        for (int jj = 0; jj < 2; jj++) {
            float2 vv = unpk(acc[i][jj]);
            int col = n0 + tx*4 + jj*2;
            if (col < N)     Cout[(size_t)row*N + col]     = vv.x + (bias ? bias[col]   : 0.f);
            if (col + 1 < N) Cout[(size_t)row*N + col + 1] = vv.y + (bias ? bias[col+1] : 0.f);
        }
    }
}

// ------------------------- fused BN (stats + normalize, 4 cols/block) ---------
__global__ void bn4_kernel(const float* __restrict__ X, float* __restrict__ Y,
                           int N, int ystride, int yoff, float* __restrict__ Yt) {
    int c0 = blockIdx.x * 4;
    int tid = threadIdx.x;
    __shared__ float4 r1[256], r2[256];
    float4 a = make_float4(0.f,0.f,0.f,0.f), b = make_float4(0.f,0.f,0.f,0.f);
    for (int r = tid; r < Bn; r += 256) {
        float4 v = *(const float4*)&X[(size_t)r*N + c0];
        a.x += v.x; a.y += v.y; a.z += v.z; a.w += v.w;
        b.x += v.x*v.x; b.y += v.y*v.y; b.z += v.z*v.z; b.w += v.w*v.w;
    }
    r1[tid] = a; r2[tid] = b; __syncthreads();
    for (int o = 128; o > 0; o >>= 1) {
        if (tid < o) {
            float4 x1 = r1[tid+o], x2 = r2[tid+o];
            r1[tid].x += x1.x; r1[tid].y += x1.y; r1[tid].z += x1.z; r1[tid].w += x1.w;
            r2[tid].x += x2.x; r2[tid].y += x2.y; r2[tid].z += x2.z; r2[tid].w += x2.w;
        }
        __syncthreads();
    }
    __shared__ float4 mm, ii;
    if (tid == 0) {
        float4 s = r1[0], ss = r2[0];
        float inv = 1.f / (float)Bn;
        float4 m = make_float4(s.x*inv, s.y*inv, s.z*inv, s.w*inv);
        mm = m;
        ii = make_float4(rsqrtf(ss.x*inv - m.x*m.x + EPSf),
                         rsqrtf(ss.y*inv - m.y*m.y + EPSf),
                         rsqrtf(ss.z*inv - m.z*m.z + EPSf),
                         rsqrtf(ss.w*inv - m.w*m.w + EPSf));
    }
    __syncthreads();
    float4 m = mm, is = ii;
    for (int r = tid; r < Bn; r += 256) {
        float4 v = *(const float4*)&X[(size_t)r*N + c0];
        float4 o = make_float4((v.x-m.x)*is.x, (v.y-m.y)*is.y, (v.z-m.z)*is.z, (v.w-m.w)*is.w);
        *(float4*)&Y[(size_t)r*ystride + yoff + c0] = o;
        if (Yt) {
            Yt[(size_t)(c0+0)*Bn + r] = o.x;
            Yt[(size_t)(c0+1)*Bn + r] = o.y;
            Yt[(size_t)(c0+2)*Bn + r] = o.z;
            Yt[(size_t)(c0+3)*Bn + r] = o.w;
        }
    }
}

// ------------------------- fc7 MMA GEMM ---------------------------------------
// C[64 x 320] per CTA; A = cross(h5) bf16 hi/lo on the fly; B pre-split.
// SMEM: h5 [300][68] f32 | A 2x(hi+lo 10240) | B 2x(51200) | pairs 19968
#define H5OFF 0
#define AOFF 81600
#define BOFF 102080
#define POFF 204480
#define FC7_SMEM (204480 + 19968)

__global__ void __launch_bounds__(256, 1) fc7_mma() {
    extern __shared__ char sm[];
    float* h5s = (float*)(sm + H5OFF);
    unsigned int* pair_s = (unsigned int*)(sm + POFF);
    int tid = threadIdx.x, lane = tid & 31, wid = tid >> 5;
    int m0 = blockIdx.x * 64;
    int ck0 = blockIdx.y * KCHUNK;
    int m_off = (wid & 1) * 32;
    int n_off = (wid >> 1) * 80;

    // h5 tile load: h5s[e][r] = h5T[e][m0+r]
    for (int idx = tid; idx < En*64; idx += 256) {
        int e = idx >> 6, r = idx & 63;
        h5s[e*68 + r] = d_h5T[(size_t)e*Bn + m0 + r];
    }
    // pair indices for this K chunk
    for (int l = tid; l < KCHUNK; l += 256) pair_s[l] = d_pairs[ck0 + l];

    uint32_t sA = smem_u32(sm + AOFF);
    uint32_t sB = smem_u32(sm + BOFF);

    int ar = (lane & 7) + ((lane >> 3) & 1) * 8;
    int ak = (lane >> 4) * 16;
    int offA0 = (m_off + ar) * 80 + ak;
    int offA1 = (m_off + 16 + ar) * 80 + ak;
    int bn = (lane & 7) + (lane >> 4) * 8;
    int bk = ((lane >> 3) & 1) * 16;
    int offB = bn * 80 + bk;

    int kp = tid & 15;
    int r0 = (tid >> 4) * 4;

    float acc[2][10][4];
    #pragma unroll
    for (int a = 0; a < 2; a++)
        #pragma unroll
        for (int b = 0; b < 10; b++)
            #pragma unroll
            for (int c = 0; c < 4; c++) acc[a][b][c] = 0.f;

    __syncthreads();   // h5s + pairs ready

    const char* srcB = (const char*)d_Bsplit + (size_t)ck0 * 2;

    // ---- stage 0: B cp.async + A gen ----
    {
        #pragma unroll
        for (int it = 0; it < 5; it++) {
            int idx = tid + it*256;
            int o = idx >> 2, c = idx & 3;
            cpa16(sB + o*80 + c*16, srcB + (size_t)o*(KPAD2*2) + c*16);
            cpa16(sB + 25600 + o*80 + c*16, srcB + BHALF + (size_t)o*(KPAD2*2) + c*16);
        }
        CP_COMMIT();
        uint2 pr = *(const uint2*)&pair_s[2*kp];
        int i0 = pr.x >> 16, j0 = pr.x & 0xffff, i1 = pr.y >> 16, j1 = pr.y & 0xffff;
        float4 A0 = *(const float4*)&h5s[i0*68 + r0];
        float4 B0 = *(const float4*)&h5s[j0*68 + r0];
        float4 A1 = *(const float4*)&h5s[i1*68 + r0];
        float4 B1 = *(const float4*)&h5s[j1*68 + r0];
        float p0[4] = {A0.x*B0.x, A0.y*B0.y, A0.z*B0.z, A0.w*B0.w};
        float p1[4] = {A1.x*B1.x, A1.y*B1.y, A1.z*B1.z, A1.w*B1.w};
        char* hi = sm + AOFF; char* lo = hi + 5120;
        #pragma unroll
        for (int r = 0; r < 4; r++) {
            uint32_t h = bfpack(p1[r], p0[r]);
            float l0 = p0[r] - __uint_as_float(h << 16);
            float l1 = p1[r] - __uint_as_float(h & 0xffff0000u);
            *(uint32_t*)(hi + (r0+r)*80 + kp*4) = h;
            *(uint32_t*)(lo + (r0+r)*80 + kp*4) = bfpack(l1, l0);
        }
    }

    for (int s = 0; s < NS; s++) {
        int sp = s & 1;
        if (s + 1 < NS) {
            uint32_t dB = sB + (sp^1)*51200;
            const char* sc = srcB + (size_t)(s+1)*64;
            #pragma unroll
            for (int it = 0; it < 5; it++) {
                int idx = tid + it*256;
                int o = idx >> 2, c = idx & 3;
                cpa16(dB + o*80 + c*16, sc + (size_t)o*(KPAD2*2) + c*16);
                cpa16(dB + 25600 + o*80 + c*16, sc + BHALF + (size_t)o*(KPAD2*2) + c*16);
            }
            CP_COMMIT();
            CP_WAIT1();
        } else {
            CP_WAIT0();
        }
        __syncthreads();   // stage s A + B visible

        uint32_t aH = sA + sp*10240, aL = aH + 5120;
        uint32_t bH = sB + sp*51200, bL = bH + 25600;
        #pragma unroll
        for (int kh = 0; kh < 2; kh++) {
            int kb = kh * 32;
            uint32_t ah0[4], ah1[4], al0[4], al1[4];
            ldsm4(ah0, aH + offA0 + kb); ldsm4(ah1, aH + offA1 + kb);
            ldsm4(al0, aL + offA0 + kb); ldsm4(al1, aL + offA1 + kb);
            #pragma unroll
            for (int gi = 0; gi < 5; gi++) {
                uint32_t bh[4], bl[4];
                uint32_t ob = (uint32_t)((n_off + gi*16)*80 + offB + kb);
                ldsm4(bh, bH + ob); ldsm4(bl, bL + ob);
                mma16816(acc[0][gi*2],   ah0, bh);
                mma16816(acc[0][gi*2+1], ah0, bh+2);
                mma16816(acc[1][gi*2],   ah1, bh);
                mma16816(acc[1][gi*2+1], ah1, bh+2);
                mma16816(acc[0][gi*2],   ah0, bl);
                mma16816(acc[0][gi*2+1], ah0, bl+2);
                mma16816(acc[1][gi*2],   ah1, bl);
                mma16816(acc[1][gi*2+1], ah1, bl+2);
                mma16816(acc[0][gi*2],   al0, bh);
                mma16816(acc[0][gi*2+1], al0, bh+2);
                mma16816(acc[1][gi*2],   al1, bh);
                mma16816(acc[1][gi*2+1], al1, bh+2);
            }
        }

        if (s + 1 < NS) {
            uint2 pr = *(const uint2*)&pair_s[(s+1)*32 + 2*kp];
            int i0 = pr.x >> 16, j0 = pr.x & 0xffff, i1 = pr.y >> 16, j1 = pr.y & 0xffff;
            float4 A0 = *(const float4*)&h5s[i0*68 + r0];
            float4 B0 = *(const float4*)&h5s[j0*68 + r0];
            float4 A1 = *(const float4*)&h5s[i1*68 + r0];
            float4 B1 = *(const float4*)&h5s[j1*68 + r0];
            float p0[4] = {A0.x*B0.x, A0.y*B0.y, A0.z*B0.z, A0.w*B0.w};
            float p1[4] = {A1.x*B1.x, A1.y*B1.y, A1.z*B1.z, A1.w*B1.w};
            char* hi = sm + AOFF + (sp^1)*10240; char* lo = hi + 5120;
            #pragma unroll
            for (int r = 0; r < 4; r++) {
                uint32_t h = bfpack(p1[r], p0[r]);
                float l0 = p0[r] - __uint_as_float(h << 16);
                float l1 = p1[r] - __uint_as_float(h & 0xffff0000u);
                *(uint32_t*)(hi + (r0+r)*80 + kp*4) = h;
                *(uint32_t*)(lo + (r0+r)*80 + kp*4) = bfpack(l1, l0);
            }
        }
        __syncthreads();
    }

    // ---- epilogue ----
    int tr = lane >> 2, tc = (lane & 3) * 2;
    #pragma unroll
    for (int mt = 0; mt < 2; mt++) {
        #pragma unroll
        for (int nt = 0; nt < 10; nt++) {
            int row = m0 + m_off + mt*16 + tr;
            int col = n_off + nt*8 + tc;
            float* a = acc[mt][nt];
            if (col < En) {
                atomicAdd(&d_h7p[(size_t)row*En + col], a[0]);
                atomicAdd(&d_h7p[(size_t)(row+8)*En + col], a[2]);
            }
            if (col + 1 < En) {
                atomicAdd(&d_h7p[(size_t)row*En + col + 1], a[1]);
                atomicAdd(&d_h7p[(size_t)(row+8)*En + col + 1], a[3]);
            }
        }
    }
}

// ------------------------- misc -----------------------------------------------
__global__ void zero_kernel(float* __restrict__ p, int n) {
    int i = blockIdx.x*256 + threadIdx.x;
    if (i < n) p[i] = 0.f;
}

// ------------------------- launch ----------------------------------------------
extern "C" void kernel_launch(void* const* d_in, const int* in_sizes, int n_in,
                              void* d_out, int out_size) {
    const float* x      = (const float*)d_in[0];
    const float* lab    = (const float*)d_in[1];
    const float* fc1_w  = (const float*)d_in[2];
    const float* fc1_b  = (const float*)d_in[3];
    const float* q1     = (const float*)d_in[4];
    const float* fc3_w  = (const float*)d_in[5];
    const float* fc3_b  = (const float*)d_in[6];
    const float* q2     = (const float*)d_in[7];
    const float* fc5_w  = (const float*)d_in[8];
    const float* fc6_w  = (const float*)d_in[10];
    const float* fc7_w  = (const float*)d_in[12];
    const float* fc8_w  = (const float*)d_in[14];
    const float* fc8_b  = (const float*)d_in[15];
    const float* v      = (const float*)d_in[16];
    float* out = (float*)d_out;

    float *ph, *ph5, *ph5T, *ph6p, *ph7p, *phcat, *pout8;
    cudaGetSymbolAddress((void**)&ph,    d_h);
    cudaGetSymbolAddress((void**)&ph5,   d_h5);
    cudaGetSymbolAddress((void**)&ph5T,  d_h5T);
    cudaGetSymbolAddress((void**)&ph6p,  d_h6p);
    cudaGetSymbolAddress((void**)&ph7p,  d_h7p);
    cudaGetSymbolAddress((void**)&phcat, d_hcat);
    cudaGetSymbolAddress((void**)&pout8, d_out8);

    cudaFuncSetAttribute(fc7_mma, cudaFuncAttributeMaxDynamicSharedMemorySize, FC7_SMEM);

    pair_kernel<<<(KPAD2 + 255)/256, 256>>>(v);
    w7bf_kernel<<<dim3((KPAD2 + 255)/256, 320), 256>>>(fc7_w);

    attn_kernel<<<1184, 256>>>(x, fc1_w, fc1_b, q1, fc3_w, fc3_b, q2);
    attn_stats_kernel<<<dim3(Sn, 2), 256>>>(q1, q2);
    pool_kernel<<<Bn, 320>>>(x);

    gemm_kernel<<<dim3(5, Bn/64), 256>>>(ph, fc5_w, ph5, nullptr, En, 600);
    bn4_kernel<<<En/4, 256>>>(ph5, ph5, En, En, 0, ph5T);   // BN(h5) in-place + h5T

    gemm_kernel<<<dim3(5, Bn/64), 256>>>(ph5, fc6_w, ph6p, nullptr, En, En);
    zero_kernel<<<(Bn*En + 255)/256, 256>>>(ph7p, Bn*En);
    fc7_mma<<<dim3(Bn/64, KSPL), 256, FC7_SMEM>>>();

    bn4_kernel<<<En/4, 256>>>(ph6p, phcat, En, 600, 0, nullptr);
    bn4_kernel<<<En/4, 256>>>(ph7p, phcat, En, 600, 300, nullptr);

    gemm_kernel<<<dim3(5, Bn/64), 256>>>(phcat, fc8_w, pout8, fc8_b, Un, 600);
    gemm_kernel<<<dim3(16, Bn/64), 256>>>(pout8, lab, out, nullptr, Ln, Un);
}

// round 11
// speedup vs baseline: 2.5473x; 1.1996x over previous
#include <cuda_runtime.h>
#include <cuda_fp16.h>
#include <math.h>
#include <stdint.h>

typedef unsigned long long ull;

#define Bn 2048
#define Sn 50
#define En 300
#define Cn 4
#define Un 300
#define Ln 1000
#define NPAIR 44850
#define EPSf  1e-5f
#define PADVAL (-4294967295.0f)

#define KPAD2 44928               /* 9 * 4992, mult of 32 */
#define KSPL 9
#define KCHUNK 4992
#define NS 156                    /* 4992/32 stages per CTA */
#define BSCALE 1024.0f
#define BSCALE_INV 0.0009765625f

// ------------------------- device scratch ------------------------------------
__device__ __align__(16) unsigned char d_Bsplit[(size_t)320 * KPAD2 * 2];  // 28.7MB fp16 hi
__device__ __align__(16) unsigned int d_pairs[KPAD2];
__device__ float d_g[NPAIR];
__device__ float d_Aq [2][Bn*Sn];
__device__ float d_Asm[2][Bn*Sn];
__device__ float d_Asq[2][Bn*Sn];
__device__ float d_sgn[Bn*Sn];
__device__ float d_m [2][Sn];
__device__ float d_is[2][Sn];
__device__ float d_Q [2];
__device__ __align__(16) float d_h   [(size_t)Bn*600];
__device__ __align__(16) float d_h5  [(size_t)Bn*En];
__device__ __align__(16) float d_h5T [(size_t)En*Bn];
__device__ __align__(16) float d_h6p [(size_t)Bn*En];
__device__ __align__(16) float d_h7p [(size_t)Bn*En];
__device__ __align__(16) float d_hcat[(size_t)Bn*600];
__device__ __align__(16) float d_out8[(size_t)Bn*Un];

// ------------------------- PTX helpers ---------------------------------------
__device__ __forceinline__ uint32_t smem_u32(const void* p) {
    uint32_t a;
    asm("{ .reg .u64 t; cvta.to.shared.u64 t, %1; cvt.u32.u64 %0, t; }" : "=r"(a) : "l"(p));
    return a;
}
__device__ __forceinline__ void ldsm4(uint32_t* r, uint32_t addr) {
    asm volatile("ldmatrix.sync.aligned.m8n8.x4.shared.b16 {%0,%1,%2,%3}, [%4];"
        : "=r"(r[0]), "=r"(r[1]), "=r"(r[2]), "=r"(r[3]) : "r"(addr));
}
__device__ __forceinline__ void mma16816(float* d, const uint32_t* a, const uint32_t* b) {
    asm volatile("mma.sync.aligned.m16n8k16.row.col.f32.f16.f16.f32 "
        "{%0,%1,%2,%3}, {%4,%5,%6,%7}, {%8,%9}, {%0,%1,%2,%3};"
        : "+f"(d[0]), "+f"(d[1]), "+f"(d[2]), "+f"(d[3])
        : "r"(a[0]), "r"(a[1]), "r"(a[2]), "r"(a[3]), "r"(b[0]), "r"(b[1]));
}
__device__ __forceinline__ void cpa16(uint32_t dst, const void* src) {
    asm volatile("cp.async.cg.shared.global [%0], [%1], 16;" :: "r"(dst), "l"(src));
}
#define CP_COMMIT() asm volatile("cp.async.commit_group;" ::: "memory")
#define CP_WAIT0()  asm volatile("cp.async.wait_group 0;" ::: "memory")
#define CP_WAIT1()  asm volatile("cp.async.wait_group 1;" ::: "memory")

__device__ __forceinline__ ull pack2(float x, float y) {
    ull r; asm("mov.b64 %0, {%1,%2};" : "=l"(r) : "f"(x), "f"(y)); return r;
}
__device__ __forceinline__ float2 unpk(ull v) {
    float2 r; asm("mov.b64 {%0,%1}, %2;" : "=f"(r.x), "=f"(r.y) : "l"(v)); return r;
}
__device__ __forceinline__ void ffma2(ull &d, ull a, ull b) {
    asm("fma.rn.f32x2 %0, %1, %2, %0;" : "+l"(d) : "l"(a), "l"(b));
}

// ------------------------- pair indices + g ----------------------------------
__device__ __forceinline__ long long pair_off(long long i) { return i * (2LL*En - i - 1) / 2; }

__global__ void pair_kernel(const float* __restrict__ v) {
    int p = blockIdx.x * 256 + threadIdx.x;
    if (p >= KPAD2) return;
    if (p >= NPAIR) { d_pairs[p] = 0; return; }
    double a = 2.0*En - 1.0;
    int i = (int)((a - sqrt(a*a - 8.0*(double)p)) * 0.5);
    if (i < 0) i = 0; if (i > En-2) i = En-2;
    while (i > 0 && pair_off(i) > p) i--;
    while (i < En-2 && pair_off(i+1) <= p) i++;
    int j = i + 1 + (int)((long long)p - pair_off(i));
    d_pairs[p] = ((unsigned)i << 16) | (unsigned)j;
    float g = 0.f;
    #pragma unroll
    for (int c = 0; c < Cn; c++) g += v[i*Cn+c] * v[j*Cn+c];
    d_g[p] = g;
}

// B prep: Bh[o][p] = fp16(fc7_w[o][p]*g[p]*1024)
__global__ void w7bf_kernel(const float* __restrict__ fc7_w) {
    int o = blockIdx.y;
    int p = blockIdx.x * 256 + threadIdx.x;
    if (p >= KPAD2) return;
    float w = 0.f;
    if (o < En && p < NPAIR) w = fc7_w[(size_t)o*NPAIR + p] * d_g[p] * BSCALE;
    __half h = __float2half_rn(w);
    unsigned short* bhi = (unsigned short*)(d_Bsplit + (size_t)o*KPAD2*2);
    bhi[p] = __half_as_ushort(h);
}

// ------------------------- attention pass 1 ----------------------------------
__global__ void attn_kernel(const float* __restrict__ x,
                            const float* __restrict__ w1, const float* __restrict__ b1,
                            const float* __restrict__ q1,
                            const float* __restrict__ w3, const float* __restrict__ b3,
                            const float* __restrict__ q3) {
    __shared__ float wsT[En*20];
    __shared__ float bs[16], qs[16];
    int tid = threadIdx.x;
    for (int idx = tid; idx < 16*En; idx += blockDim.x) {
        int t = idx / En, e = idx % En;
        float val = (t < 8) ? w1[t*En + e] : w3[(t-8)*En + e];
        wsT[e*20 + t] = val;
    }
    if (tid < 8)       { bs[tid] = b1[tid];   qs[tid] = q1[tid]; }
    else if (tid < 16) { bs[tid] = b3[tid-8]; qs[tid] = q3[tid-8]; }
    __syncthreads();
    int lane = tid & 31;
    int gw = blockIdx.x * (blockDim.x >> 5) + (tid >> 5);
    int nw = gridDim.x * (blockDim.x >> 5);
    for (int item = gw; item < Bn*Sn; item += nw) {
        const float* xp = x + (size_t)item * En;
        float dot[16];
        #pragma unroll
        for (int t = 0; t < 16; t++) dot[t] = 0.f;
        float ab = 0.f;
        for (int e = lane; e < En; e += 32) {
            float xv = xp[e];
            ab += fabsf(xv);
            const float4* wp = (const float4*)&wsT[e*20];
            float4 wa = wp[0], wb = wp[1], wc = wp[2], wd = wp[3];
            dot[0]  += xv*wa.x; dot[1]  += xv*wa.y; dot[2]  += xv*wa.z; dot[3]  += xv*wa.w;
            dot[4]  += xv*wb.x; dot[5]  += xv*wb.y; dot[6]  += xv*wb.z; dot[7]  += xv*wb.w;
            dot[8]  += xv*wc.x; dot[9]  += xv*wc.y; dot[10] += xv*wc.z; dot[11] += xv*wc.w;
            dot[12] += xv*wd.x; dot[13] += xv*wd.y; dot[14] += xv*wd.z; dot[15] += xv*wd.w;
        }
        #pragma unroll
        for (int o = 16; o > 0; o >>= 1) {
            ab += __shfl_down_sync(0xffffffffu, ab, o);
            #pragma unroll
            for (int t = 0; t < 16; t++) dot[t] += __shfl_down_sync(0xffffffffu, dot[t], o);
        }
        if (lane == 0) {
            #pragma unroll
            for (int h = 0; h < 2; h++) {
                float asum = 0.f, asq = 0.f, aq = 0.f;
                #pragma unroll
                for (int t = 0; t < 8; t++) {
                    float av = dot[h*8+t] + bs[h*8+t];
                    av = av > 0.f ? av : 0.f;
                    asum += av; asq += av*av; aq += av * qs[h*8+t];
                }
                d_Aq[h][item] = aq; d_Asm[h][item] = asum; d_Asq[h][item] = asq;
            }
            d_sgn[item] = ab;
        }
    }
}

__global__ void attn_stats_kernel(const float* __restrict__ q1, const float* __restrict__ q3) {
    int s = blockIdx.x, h = blockIdx.y;
    __shared__ float r1[256], r2[256];
    float a = 0.f, b = 0.f;
    for (int bb = threadIdx.x; bb < Bn; bb += 256) {
        a += d_Asm[h][bb*Sn + s];
        b += d_Asq[h][bb*Sn + s];
    }
    r1[threadIdx.x] = a; r2[threadIdx.x] = b; __syncthreads();
    for (int o = 128; o > 0; o >>= 1) {
        if (threadIdx.x < o) { r1[threadIdx.x] += r1[threadIdx.x+o]; r2[threadIdx.x] += r2[threadIdx.x+o]; }
        __syncthreads();
    }
    if (threadIdx.x == 0) {
        float n = (float)(Bn * 8);
        float m = r1[0] / n;
        float var = r2[0] / n - m*m;
        d_m[h][s] = m;
        d_is[h][s] = rsqrtf(var + EPSf);
        if (s == 0) {
            const float* q = h ? q3 : q1;
            float Q = 0.f;
            for (int t = 0; t < 8; t++) Q += q[t];
            d_Q[h] = Q;
        }
    }
}

__global__ void pool_kernel(const float* __restrict__ x) {
    int b = blockIdx.x;
    __shared__ float w0[Sn], w1s[Sn];
    int tid = threadIdx.x;
    if (tid < Sn) {
        int item = b*Sn + tid;
        float sg = d_sgn[item];
        float s0 = (sg == 0.f) ? PADVAL : (d_Aq[0][item] - d_m[0][tid]*d_Q[0]) * d_is[0][tid];
        float s1 = (sg == 0.f) ? PADVAL : (d_Aq[1][item] - d_m[1][tid]*d_Q[1]) * d_is[1][tid];
        w0[tid] = s0; w1s[tid] = s1;
    }
    __syncthreads();
    float mx0 = -INFINITY, mx1 = -INFINITY;
    for (int s = 0; s < Sn; s++) { mx0 = fmaxf(mx0, w0[s]); mx1 = fmaxf(mx1, w1s[s]); }
    __syncthreads();
    if (tid < Sn) { w0[tid] = expf(w0[tid]-mx0); w1s[tid] = expf(w1s[tid]-mx1); }
    __syncthreads();
    float sm0 = 0.f, sm1 = 0.f;
    for (int s = 0; s < Sn; s++) { sm0 += w0[s]; sm1 += w1s[s]; }
    float inv0 = 1.f/sm0, inv1 = 1.f/sm1;
    if (tid < En) {
        float a0 = 0.f, a1 = 0.f;
        const float* xp = x + (size_t)b*Sn*En + tid;
        for (int s = 0; s < Sn; s++) {
            float xv = xp[(size_t)s*En];
            a0 += w0[s]*xv; a1 += w1s[s]*xv;
        }
        d_h[(size_t)b*600 + tid]       = a0*inv0;
        d_h[(size_t)b*600 + 300 + tid] = a1*inv1;
    }
}

// ------------------------- small SGEMM (f32x2) --------------------------------
__global__ void gemm_kernel(const float* __restrict__ A, const float* __restrict__ W,
                            float* __restrict__ Cout, const float* __restrict__ bias,
                            int N, int K) {
    __shared__ float As[12*68];
    __shared__ float Ws[12*68];
    int m0 = blockIdx.y * 64, n0 = blockIdx.x * 64;
    int tid = threadIdx.x;
    int ty = tid >> 4, tx = tid & 15;
    ull acc[4][2];
    #pragma unroll
    for (int i = 0; i < 4; i++) { acc[i][0] = 0ULL; acc[i][1] = 0ULL; }
    for (int kc = 0; kc < K; kc += 12) {
        for (int idx = tid; idx < 64*12; idx += 256) {
            int r = idx / 12, kk = idx % 12;
            As[kk*68 + r] = A[(size_t)(m0+r)*K + kc + kk];
        }
        for (int idx = tid; idx < 64*12; idx += 256) {
            int c = idx / 12, kk = idx % 12;
            int col = n0 + c;
            Ws[kk*68 + c] = (col < N) ? W[(size_t)col*K + kc + kk] : 0.f;
        }
        __syncthreads();
        #pragma unroll
        for (int kk = 0; kk < 12; kk++) {
            float4 av = *(const float4*)&As[kk*68 + ty*4];
            float4 bv = *(const float4*)&Ws[kk*68 + tx*4];
            ull b01 = pack2(bv.x, bv.y), b23 = pack2(bv.z, bv.w);
            ull a;
            a = pack2(av.x, av.x); ffma2(acc[0][0], a, b01); ffma2(acc[0][1], a, b23);
            a = pack2(av.y, av.y); ffma2(acc[1][0], a, b01); ffma2(acc[1][1], a, b23);
            a = pack2(av.z, av.z); ffma2(acc[2][0], a, b01); ffma2(acc[2][1], a, b23);
            a = pack2(av.w, av.w); ffma2(acc[3][0], a, b01); ffma2(acc[3][1], a, b23);
        }
        __syncthreads();
    }
    #pragma unroll
    for (int i = 0; i < 4; i++) {
        int row = m0 + ty*4 + i;
        #pragma unroll
        for (int jj = 0; jj < 2; jj++) {
            float2 vv = unpk(acc[i][jj]);
            int col = n0 + tx*4 + jj*2;
            if (col < N)     Cout[(size_t)row*N + col]     = vv.x + (bias ? bias[col]   : 0.f);
            if (col + 1 < N) Cout[(size_t)row*N + col + 1] = vv.y + (bias ? bias[col+1] : 0.f);
        }
    }
}

// ------------------------- fused BN (stats + normalize, 4 cols/block) ---------
__global__ void bn4_kernel(const float* __restrict__ X, float* __restrict__ Y,
                           int N, int ystride, int yoff, float* __restrict__ Yt) {
    int c0 = blockIdx.x * 4;
    int tid = threadIdx.x;
    __shared__ float4 r1[256], r2[256];
    float4 a = make_float4(0.f,0.f,0.f,0.f), b = make_float4(0.f,0.f,0.f,0.f);
    for (int r = tid; r < Bn; r += 256) {
        float4 v = *(const float4*)&X[(size_t)r*N + c0];
        a.x += v.x; a.y += v.y; a.z += v.z; a.w += v.w;
        b.x += v.x*v.x; b.y += v.y*v.y; b.z += v.z*v.z; b.w += v.w*v.w;
    }
    r1[tid] = a; r2[tid] = b; __syncthreads();
    for (int o = 128; o > 0; o >>= 1) {
        if (tid < o) {
            float4 x1 = r1[tid+o], x2 = r2[tid+o];
            r1[tid].x += x1.x; r1[tid].y += x1.y; r1[tid].z += x1.z; r1[tid].w += x1.w;
            r2[tid].x += x2.x; r2[tid].y += x2.y; r2[tid].z += x2.z; r2[tid].w += x2.w;
        }
        __syncthreads();
    }
    __shared__ float4 mm, ii;
    if (tid == 0) {
        float4 s = r1[0], ss = r2[0];
        float inv = 1.f / (float)Bn;
        float4 m = make_float4(s.x*inv, s.y*inv, s.z*inv, s.w*inv);
        mm = m;
        ii = make_float4(rsqrtf(ss.x*inv - m.x*m.x + EPSf),
                         rsqrtf(ss.y*inv - m.y*m.y + EPSf),
                         rsqrtf(ss.z*inv - m.z*m.z + EPSf),
                         rsqrtf(ss.w*inv - m.w*m.w + EPSf));
    }
    __syncthreads();
    float4 m = mm, is = ii;
    for (int r = tid; r < Bn; r += 256) {
        float4 v = *(const float4*)&X[(size_t)r*N + c0];
        float4 o = make_float4((v.x-m.x)*is.x, (v.y-m.y)*is.y, (v.z-m.z)*is.z, (v.w-m.w)*is.w);
        *(float4*)&Y[(size_t)r*ystride + yoff + c0] = o;
        if (Yt) {
            Yt[(size_t)(c0+0)*Bn + r] = o.x;
            Yt[(size_t)(c0+1)*Bn + r] = o.y;
            Yt[(size_t)(c0+2)*Bn + r] = o.z;
            Yt[(size_t)(c0+3)*Bn + r] = o.w;
        }
    }
}

// ------------------------- fc7 MMA GEMM ---------------------------------------
// 2-pass fp16: C = (Ah+Al)·Bh, B pre-scaled x1024, epilogue x 1/1024.
// SMEM: h5 [300][68] f32 | A 2x(hi 5120 + lo 5120) | B 2x25600 | pairs 19968
#define H5OFF 0
#define AOFF 81600
#define BOFF 102080
#define POFF 153280
#define FC7_SMEM (153280 + 19968)

__global__ void __launch_bounds__(256, 1) fc7_mma() {
    extern __shared__ char sm[];
    float* h5s = (float*)(sm + H5OFF);
    unsigned int* pair_s = (unsigned int*)(sm + POFF);
    int tid = threadIdx.x, lane = tid & 31, wid = tid >> 5;
    int m0 = blockIdx.x * 64;
    int ck0 = blockIdx.y * KCHUNK;
    int m_off = (wid & 1) * 32;
    int n_off = (wid >> 1) * 80;

    for (int idx = tid; idx < En*64; idx += 256) {
        int e = idx >> 6, r = idx & 63;
        h5s[e*68 + r] = d_h5T[(size_t)e*Bn + m0 + r];
    }
    for (int l = tid; l < KCHUNK; l += 256) pair_s[l] = d_pairs[ck0 + l];

    uint32_t sA = smem_u32(sm + AOFF);
    uint32_t sB = smem_u32(sm + BOFF);

    int ar = (lane & 7) + ((lane >> 3) & 1) * 8;
    int ak = (lane >> 4) * 16;
    int offA0 = (m_off + ar) * 80 + ak;
    int offA1 = (m_off + 16 + ar) * 80 + ak;
    int bn = (lane & 7) + (lane >> 4) * 8;
    int bk = ((lane >> 3) & 1) * 16;
    int offB = bn * 80 + bk;

    int kp = tid & 15;
    int r0 = (tid >> 4) * 4;

    float acc[2][10][4];
    #pragma unroll
    for (int a = 0; a < 2; a++)
        #pragma unroll
        for (int b = 0; b < 10; b++)
            #pragma unroll
            for (int c = 0; c < 4; c++) acc[a][b][c] = 0.f;

    __syncthreads();   // h5s + pairs ready

    const char* srcB = (const char*)d_Bsplit + (size_t)ck0 * 2;

    // ---- stage 0: B cp.async + A gen ----
    {
        #pragma unroll
        for (int it = 0; it < 5; it++) {
            int idx = tid + it*256;
            int o = idx >> 2, c = idx & 3;
            cpa16(sB + o*80 + c*16, srcB + (size_t)o*(KPAD2*2) + c*16);
        }
        CP_COMMIT();
        uint2 pr = *(const uint2*)&pair_s[2*kp];
        int i0 = pr.x >> 16, j0 = pr.x & 0xffff, i1 = pr.y >> 16, j1 = pr.y & 0xffff;
        float4 A0 = *(const float4*)&h5s[i0*68 + r0];
        float4 B0 = *(const float4*)&h5s[j0*68 + r0];
        float4 A1 = *(const float4*)&h5s[i1*68 + r0];
        float4 B1 = *(const float4*)&h5s[j1*68 + r0];
        float p0[4] = {A0.x*B0.x, A0.y*B0.y, A0.z*B0.z, A0.w*B0.w};
        float p1[4] = {A1.x*B1.x, A1.y*B1.y, A1.z*B1.z, A1.w*B1.w};
        char* hi = sm + AOFF; char* lo = hi + 5120;
        #pragma unroll
        for (int r = 0; r < 4; r++) {
            __half h0 = __float2half_rn(p0[r]);
            __half h1 = __float2half_rn(p1[r]);
            *(__half2*)(hi + (r0+r)*80 + kp*4) = __halves2half2(h0, h1);
            __half l0 = __float2half_rn(p0[r] - __half2float(h0));
            __half l1 = __float2half_rn(p1[r] - __half2float(h1));
            *(__half2*)(lo + (r0+r)*80 + kp*4) = __halves2half2(l0, l1);
        }
    }

    for (int s = 0; s < NS; s++) {
        int sp = s & 1;
        if (s + 1 < NS) {
            uint32_t dB = sB + (sp^1)*25600;
            const char* sc = srcB + (size_t)(s+1)*64;
            #pragma unroll
            for (int it = 0; it < 5; it++) {
                int idx = tid + it*256;
                int o = idx >> 2, c = idx & 3;
                cpa16(dB + o*80 + c*16, sc + (size_t)o*(KPAD2*2) + c*16);
            }
            CP_COMMIT();
            CP_WAIT1();
        } else {
            CP_WAIT0();
        }
        __syncthreads();   // stage s A + B visible

        uint32_t aH = sA + sp*10240, aL = aH + 5120;
        uint32_t bH = sB + sp*25600;
        #pragma unroll
        for (int kh = 0; kh < 2; kh++) {
            int kb = kh * 32;
            uint32_t ah0[4], ah1[4], al0[4], al1[4];
            ldsm4(ah0, aH + offA0 + kb); ldsm4(ah1, aH + offA1 + kb);
            ldsm4(al0, aL + offA0 + kb); ldsm4(al1, aL + offA1 + kb);
            #pragma unroll
            for (int gi = 0; gi < 5; gi++) {
                uint32_t bh[4];
                uint32_t ob = (uint32_t)((n_off + gi*16)*80 + offB + kb);
                ldsm4(bh, bH + ob);
                mma16816(acc[0][gi*2],   ah0, bh);
                mma16816(acc[0][gi*2+1], ah0, bh+2);
                mma16816(acc[1][gi*2],   ah1, bh);
                mma16816(acc[1][gi*2+1], ah1, bh+2);
                mma16816(acc[0][gi*2],   al0, bh);
                mma16816(acc[0][gi*2+1], al0, bh+2);
                mma16816(acc[1][gi*2],   al1, bh);
                mma16816(acc[1][gi*2+1], al1, bh+2);
            }
        }

        if (s + 1 < NS) {
            uint2 pr = *(const uint2*)&pair_s[(s+1)*32 + 2*kp];
            int i0 = pr.x >> 16, j0 = pr.x & 0xffff, i1 = pr.y >> 16, j1 = pr.y & 0xffff;
            float4 A0 = *(const float4*)&h5s[i0*68 + r0];
            float4 B0 = *(const float4*)&h5s[j0*68 + r0];
            float4 A1 = *(const float4*)&h5s[i1*68 + r0];
            float4 B1 = *(const float4*)&h5s[j1*68 + r0];
            float p0[4] = {A0.x*B0.x, A0.y*B0.y, A0.z*B0.z, A0.w*B0.w};
            float p1[4] = {A1.x*B1.x, A1.y*B1.y, A1.z*B1.z, A1.w*B1.w};
            char* hi = sm + AOFF + (sp^1)*10240; char* lo = hi + 5120;
            #pragma unroll
            for (int r = 0; r < 4; r++) {
                __half h0 = __float2half_rn(p0[r]);
                __half h1 = __float2half_rn(p1[r]);
                *(__half2*)(hi + (r0+r)*80 + kp*4) = __halves2half2(h0, h1);
                __half l0 = __float2half_rn(p0[r] - __half2float(h0));
                __half l1 = __float2half_rn(p1[r] - __half2float(h1));
                *(__half2*)(lo + (r0+r)*80 + kp*4) = __halves2half2(l0, l1);
            }
        }
        __syncthreads();
    }

    // ---- epilogue (unscale by 1/1024) ----
    int tr = lane >> 2, tc = (lane & 3) * 2;
    #pragma unroll
    for (int mt = 0; mt < 2; mt++) {
        #pragma unroll
        for (int nt = 0; nt < 10; nt++) {
            int row = m0 + m_off + mt*16 + tr;
            int col = n_off + nt*8 + tc;
            float* a = acc[mt][nt];
            if (col < En) {
                atomicAdd(&d_h7p[(size_t)row*En + col], a[0]*BSCALE_INV);
                atomicAdd(&d_h7p[(size_t)(row+8)*En + col], a[2]*BSCALE_INV);
            }
            if (col + 1 < En) {
                atomicAdd(&d_h7p[(size_t)row*En + col + 1], a[1]*BSCALE_INV);
                atomicAdd(&d_h7p[(size_t)(row+8)*En + col + 1], a[3]*BSCALE_INV);
            }
        }
    }
}

// ------------------------- misc -----------------------------------------------
__global__ void zero_kernel(float* __restrict__ p, int n) {
    int i = blockIdx.x*256 + threadIdx.x;
    if (i < n) p[i] = 0.f;
}

// ------------------------- launch ----------------------------------------------
extern "C" void kernel_launch(void* const* d_in, const int* in_sizes, int n_in,
                              void* d_out, int out_size) {
    const float* x      = (const float*)d_in[0];
    const float* lab    = (const float*)d_in[1];
    const float* fc1_w  = (const float*)d_in[2];
    const float* fc1_b  = (const float*)d_in[3];
    const float* q1     = (const float*)d_in[4];
    const float* fc3_w  = (const float*)d_in[5];
    const float* fc3_b  = (const float*)d_in[6];
    const float* q2     = (const float*)d_in[7];
    const float* fc5_w  = (const float*)d_in[8];
    const float* fc6_w  = (const float*)d_in[10];
    const float* fc7_w  = (const float*)d_in[12];
    const float* fc8_w  = (const float*)d_in[14];
    const float* fc8_b  = (const float*)d_in[15];
    const float* v      = (const float*)d_in[16];
    float* out = (float*)d_out;

    float *ph, *ph5, *ph5T, *ph6p, *ph7p, *phcat, *pout8;
    cudaGetSymbolAddress((void**)&ph,    d_h);
    cudaGetSymbolAddress((void**)&ph5,   d_h5);
    cudaGetSymbolAddress((void**)&ph5T,  d_h5T);
    cudaGetSymbolAddress((void**)&ph6p,  d_h6p);
    cudaGetSymbolAddress((void**)&ph7p,  d_h7p);
    cudaGetSymbolAddress((void**)&phcat, d_hcat);
    cudaGetSymbolAddress((void**)&pout8, d_out8);

    cudaFuncSetAttribute(fc7_mma, cudaFuncAttributeMaxDynamicSharedMemorySize, FC7_SMEM);

    pair_kernel<<<(KPAD2 + 255)/256, 256>>>(v);
    w7bf_kernel<<<dim3((KPAD2 + 255)/256, 320), 256>>>(fc7_w);

    attn_kernel<<<1184, 256>>>(x, fc1_w, fc1_b, q1, fc3_w, fc3_b, q2);
    attn_stats_kernel<<<dim3(Sn, 2), 256>>>(q1, q2);
    pool_kernel<<<Bn, 320>>>(x);

    gemm_kernel<<<dim3(5, Bn/64), 256>>>(ph, fc5_w, ph5, nullptr, En, 600);
    bn4_kernel<<<En/4, 256>>>(ph5, ph5, En, En, 0, ph5T);   // BN(h5) in-place + h5T

    gemm_kernel<<<dim3(5, Bn/64), 256>>>(ph5, fc6_w, ph6p, nullptr, En, En);
    zero_kernel<<<(Bn*En + 255)/256, 256>>>(ph7p, Bn*En);
    fc7_mma<<<dim3(Bn/64, KSPL), 256, FC7_SMEM>>>();

    bn4_kernel<<<En/4, 256>>>(ph6p, phcat, En, 600, 0, nullptr);
    bn4_kernel<<<En/4, 256>>>(ph7p, phcat, En, 600, 300, nullptr);

    gemm_kernel<<<dim3(5, Bn/64), 256>>>(phcat, fc8_w, pout8, fc8_b, Un, 600);
    gemm_kernel<<<dim3(16, Bn/64), 256>>>(pout8, lab, out, nullptr, Ln, Un);
}